// round 13
// baseline (speedup 1.0000x reference)
#include <cuda_runtime.h>
#include <cuda_bf16.h>
#include <cstdint>

// Problem constants
#define NPOS 2048   // B*S
#define DM   512
#define NH   8
#define DH   64
#define TT   32

typedef __nv_bfloat16 bf16;

// Scratch (device globals)
__device__ float g_P  [NPOS * NH * DM];   // linear: [i][h][512]
__device__ int   g_AM [NPOS];
__device__ int   g_MaskMode;
__device__ __align__(16) bf16 g_SRCh[NPOS * DM],      g_SRCl[NPOS * DM];
__device__ __align__(16) bf16 g_Qh  [NPOS * DM],      g_Ql  [NPOS * DM];
__device__ __align__(16) bf16 g_Uh  [NPOS * NH * DM], g_Ul  [NPOS * NH * DM];
__device__ __align__(16) bf16 g_CTXh[NPOS * DM],      g_CTXl[NPOS * DM];
__device__ __align__(16) bf16 g_WQh [DM * DM],        g_WQl [DM * DM];
__device__ __align__(16) bf16 g_WKTh[NH * DM * DH],   g_WKTl[NH * DM * DH];
__device__ __align__(16) bf16 g_WVh [DM * DM],        g_WVl [DM * DM];
__device__ __align__(16) bf16 g_WOh [DM * DM],        g_WOl [DM * DM];

// ======================= helpers ===========================================
__device__ __forceinline__ uint32_t smem_u32(const void* p) {
    uint32_t a;
    asm("{ .reg .u64 t; cvta.to.shared.u64 t, %1; cvt.u32.u64 %0, t; }"
        : "=r"(a) : "l"(p));
    return a;
}
__device__ __forceinline__ void ldm_x4(uint32_t* r, uint32_t addr) {
    asm volatile("ldmatrix.sync.aligned.m8n8.x4.shared.b16 {%0,%1,%2,%3}, [%4];"
                 : "=r"(r[0]), "=r"(r[1]), "=r"(r[2]), "=r"(r[3]) : "r"(addr));
}
__device__ __forceinline__ void mma_bf16(float* d, const uint32_t* a,
                                         uint32_t b0, uint32_t b1) {
    asm volatile(
        "mma.sync.aligned.m16n8k16.row.col.f32.bf16.bf16.f32 "
        "{%0,%1,%2,%3}, {%4,%5,%6,%7}, {%8,%9}, {%0,%1,%2,%3};"
        : "+f"(d[0]), "+f"(d[1]), "+f"(d[2]), "+f"(d[3])
        : "r"(a[0]), "r"(a[1]), "r"(a[2]), "r"(a[3]), "r"(b0), "r"(b1));
}
#define CP_ASYNC16(dst, src) \
    asm volatile("cp.async.cg.shared.global [%0], [%1], 16;" \
                 :: "r"(dst), "l"(src) : "memory")
#define CP_COMMIT() asm volatile("cp.async.commit_group;" ::: "memory")
#define CP_WAIT1()  asm volatile("cp.async.wait_group 1;" ::: "memory")
#define CP_WAIT0()  asm volatile("cp.async.wait_group 0;" ::: "memory")

__device__ __forceinline__ unsigned pack_bf2(bf16 a, bf16 b) {
    __nv_bfloat162 t; t.x = a; t.y = b;
    return *reinterpret_cast<unsigned*>(&t);
}
__device__ __forceinline__ void split4(float4 v, uint2& hi, uint2& lo) {
    bf16 hx = __float2bfloat16(v.x), hy = __float2bfloat16(v.y);
    bf16 hz = __float2bfloat16(v.z), hw = __float2bfloat16(v.w);
    bf16 lx = __float2bfloat16(v.x - __bfloat162float(hx));
    bf16 ly = __float2bfloat16(v.y - __bfloat162float(hy));
    bf16 lz = __float2bfloat16(v.z - __bfloat162float(hz));
    bf16 lw = __float2bfloat16(v.w - __bfloat162float(hw));
    hi = make_uint2(pack_bf2(hx, hy), pack_bf2(hz, hw));
    lo = make_uint2(pack_bf2(lx, ly), pack_bf2(lz, lw));
}
__device__ __forceinline__ void split2_store(float x, float y,
                                             bf16* hi, bf16* lo, size_t off) {
    bf16 hx = __float2bfloat16(x), hy = __float2bfloat16(y);
    bf16 lx = __float2bfloat16(x - __bfloat162float(hx));
    bf16 ly = __float2bfloat16(y - __bfloat162float(hy));
    *(uint32_t*)&hi[off] = pack_bf2(hx, hy);
    *(uint32_t*)&lo[off] = pack_bf2(lx, ly);
}

// ======================= fused prep kernel =================================
__global__ __launch_bounds__(256) void prep_all(
    const float* __restrict__ src, const float* __restrict__ ipw,
    const float* __restrict__ opw, const void* __restrict__ mask,
    bf16* __restrict__ SRCh, bf16* __restrict__ SRCl,
    bf16* __restrict__ WQh,  bf16* __restrict__ WQl,
    bf16* __restrict__ WVh,  bf16* __restrict__ WVl,
    bf16* __restrict__ WOh,  bf16* __restrict__ WOl,
    bf16* __restrict__ WKTh, bf16* __restrict__ WKTl,
    int* __restrict__ mode)
{
    const int b = blockIdx.x, tid = threadIdx.x;
    if (b < 1792) {
        const float* x; bf16 *hi, *lo; int i;
        if (b < 1024)      { x = src;             hi = SRCh; lo = SRCl; i = b * 256 + tid; }
        else if (b < 1280) { x = ipw;             hi = WQh;  lo = WQl;  i = (b - 1024) * 256 + tid; }
        else if (b < 1536) { x = ipw + 1024*512;  hi = WVh;  lo = WVl;  i = (b - 1280) * 256 + tid; }
        else               { x = opw;             hi = WOh;  lo = WOl;  i = (b - 1536) * 256 + tid; }
        float4 v = ((const float4*)x)[i];
        uint2 h, l; split4(v, h, l);
        ((uint2*)hi)[i] = h; ((uint2*)lo)[i] = l;
    } else if (b < 2048) {
        __shared__ float t[32][33];
        const int r = b - 1792;
        const int h = r >> 5, nb = (r & 15) * 32, kb = ((r >> 4) & 1) * 32;
        const int x = tid & 31, y = tid >> 5;
        for (int i = y; i < 32; i += 8)
            t[i][x] = ipw[(size_t)(512 + h * 64 + kb + i) * 512 + nb + x];
        __syncthreads();
        for (int i = y; i < 32; i += 8) {
            float v = t[x][i];
            size_t o = (size_t)h * (512 * 64) + (size_t)(nb + i) * 64 + kb + x;
            bf16 bh = __float2bfloat16(v);
            WKTh[o] = bh;
            WKTl[o] = __float2bfloat16(v - __bfloat162float(bh));
        }
    } else {
        __shared__ int flags[2];
        if (tid < 2) flags[tid] = 0;
        __syncthreads();
        const unsigned* w = (const unsigned*)mask;
        for (int j = tid; j < 16384; j += 256) {
            unsigned v = w[j];
            if (v == 0x3F800000u) atomicOr(&flags[0], 1);
            else if (v > 1u)      atomicOr(&flags[1], 1);
        }
        __syncthreads();
        if (tid == 0) *mode = flags[0] ? 2 : (flags[1] ? 0 : 1);
    }
}

// ======================= HMMA GEMM (cp.async, MT x 64 tile) ================
// C[M,N] = A[M,K] @ B[N,K]^T + bias; pre-split bf16 hi/lo planes; split
// product hi*hi + hi*lo + lo*hi. MT=128: 4Mx2N warps; MT=64: 2Mx4N warps.
// EMIT bit0: fp32 linear C. EMIT bit1: bf16 hi/lo planes.
template <int MT, int EMIT, bool ZMASK>
__global__ __launch_bounds__(256, (MT == 64) ? 3 : 2) void hmma_gemm(
    const bf16* __restrict__ Ahi, const bf16* __restrict__ Alo, int lda, int aoz,
    const bf16* __restrict__ Bhi, const bf16* __restrict__ Blo, int ldb, int boz,
    float* __restrict__ C, bf16* __restrict__ Chi, bf16* __restrict__ Clo,
    int ldc, int coz,
    const float* __restrict__ bias, int bioz,
    int K, const int* __restrict__ rmask)
{
    constexpr int RS  = 80;
    constexpr int APL = MT * RS;
    constexpr int BPL = 64 * RS;
    constexpr int STG = 2 * APL + 2 * BPL;
    constexpr int NTW = (MT == 128) ? 32 : 16;
    constexpr int NT8 = NTW / 8;

    extern __shared__ char smem[];
    const uint32_t sbase = smem_u32(smem);

    const int z = blockIdx.z;
    Ahi += (size_t)z * aoz;  Alo += (size_t)z * aoz;
    Bhi += (size_t)z * boz;  Blo += (size_t)z * boz;
    const int m0 = blockIdx.x * MT, n0 = blockIdx.y * 64;

    const int tid = threadIdx.x, lane = tid & 31, wid = tid >> 5;
    const int wm = (MT == 128) ? (wid & 3) : (wid & 1);
    const int wn = (MT == 128) ? (wid >> 2) : (wid >> 1);

    const int sr = tid >> 2, sc = tid & 3;

    const int g = lane >> 3, lr = lane & 7;
    const int grow = (g & 1) * 8 + lr;
    const int gk   = (g >> 1) * 16;

    float acc[2][NT8][4] = {};
    const int nst = K >> 5;

    auto issue = [&](int s) {
        const int kt = s << 5;
        const uint32_t sb = sbase + (s % 3) * STG;
        #pragma unroll
        for (int r = 0; r < MT / 64; r++) {
            const int row = sr + r * 64;
            CP_ASYNC16(sb + row * RS + sc * 16,
                       &Ahi[(size_t)(m0 + row) * lda + kt + sc * 8]);
            CP_ASYNC16(sb + APL + row * RS + sc * 16,
                       &Alo[(size_t)(m0 + row) * lda + kt + sc * 8]);
        }
        CP_ASYNC16(sb + 2 * APL + sr * RS + sc * 16,
                   &Bhi[(size_t)(n0 + sr) * ldb + kt + sc * 8]);
        CP_ASYNC16(sb + 2 * APL + BPL + sr * RS + sc * 16,
                   &Blo[(size_t)(n0 + sr) * ldb + kt + sc * 8]);
    };

    issue(0); CP_COMMIT();
    if (nst > 1) issue(1);
    CP_COMMIT();

    for (int s = 0; s < nst; s++) {
        CP_WAIT1();
        __syncthreads();
        if (s + 2 < nst) issue(s + 2);
        CP_COMMIT();

        const uint32_t sb = sbase + (s % 3) * STG;
        const uint32_t ahs = sb, als = sb + APL;
        const uint32_t bhs = sb + 2 * APL, bls = bhs + BPL;
        #pragma unroll
        for (int kk = 0; kk < 2; kk++) {
            const int kb = kk * 32 + gk;
            uint32_t a_hi[2][4], a_lo[2][4], b_hi[NT8 / 2][4], b_lo[NT8 / 2][4];
            #pragma unroll
            for (int mt = 0; mt < 2; mt++) {
                const uint32_t ro = (wm * 32 + mt * 16 + grow) * RS + kb;
                ldm_x4(a_hi[mt], ahs + ro);
                ldm_x4(a_lo[mt], als + ro);
            }
            #pragma unroll
            for (int ng = 0; ng < NT8 / 2; ng++) {
                const uint32_t ro = (wn * NTW + ng * 16 + grow) * RS + kb;
                ldm_x4(b_hi[ng], bhs + ro);
                ldm_x4(b_lo[ng], bls + ro);
            }
            #pragma unroll
            for (int mt = 0; mt < 2; mt++)
                #pragma unroll
                for (int nt = 0; nt < NT8; nt++) {
                    const int ng = nt >> 1, sel = nt & 1;
                    const uint32_t bh0 = b_hi[ng][sel], bh1 = b_hi[ng][sel + 2];
                    const uint32_t bl0 = b_lo[ng][sel], bl1 = b_lo[ng][sel + 2];
                    mma_bf16(acc[mt][nt], a_hi[mt], bh0, bh1);
                    mma_bf16(acc[mt][nt], a_hi[mt], bl0, bl1);
                    mma_bf16(acc[mt][nt], a_lo[mt], bh0, bh1);
                }
        }
    }

    // epilogue
    const int qr = lane >> 2, qc = (lane & 3) * 2;
    #pragma unroll
    for (int mt = 0; mt < 2; mt++) {
        const int r0 = m0 + wm * 32 + mt * 16 + qr;
        const bool z0 = ZMASK ? (rmask[r0] != 0)     : false;
        const bool z1 = ZMASK ? (rmask[r0 + 8] != 0) : false;
        #pragma unroll
        for (int nt = 0; nt < NT8; nt++) {
            const int c = n0 + wn * NTW + nt * 8 + qc;
            float b0 = 0.f, b1 = 0.f;
            if (bias) { b0 = bias[(size_t)z * bioz + c]; b1 = bias[(size_t)z * bioz + c + 1]; }
            float2 v0 = make_float2(acc[mt][nt][0] + b0, acc[mt][nt][1] + b1);
            float2 v1 = make_float2(acc[mt][nt][2] + b0, acc[mt][nt][3] + b1);
            if (z0) v0 = make_float2(0.f, 0.f);
            if (z1) v1 = make_float2(0.f, 0.f);
            const size_t o0 = (size_t)z * coz + (size_t)r0 * ldc + c;
            const size_t o1 = o0 + (size_t)8 * ldc;
            if (EMIT & 1) { *(float2*)&C[o0] = v0; *(float2*)&C[o1] = v1; }
            if (EMIT & 2) {
                split2_store(v0.x, v0.y, Chi, Clo, o0);
                split2_store(v1.x, v1.y, Chi, Clo, o1);
            }
        }
    }
}

// ======================= fused attention core (v6: 512 threads) ============
// Same structure as v5 but 512 threads/block for 32 warps/SM at 2 CTAs/SM.
// Logits: 16 warps = 16 k-slabs of 8 float4. u-phase: thread = (k4, head-pair).
__global__ __launch_bounds__(512, 2) void attn_core(
    const float* __restrict__ tgt,
    const bf16* __restrict__ Qh, const bf16* __restrict__ Ql,
    const float* __restrict__ P,
    const void* __restrict__ mask_raw,
    const int* __restrict__ mask_mode,
    const float* __restrict__ ipb,
    bf16* __restrict__ Uhi, bf16* __restrict__ Ulo,
    int* __restrict__ allm)
{
    extern __shared__ float sm[];
    float4* tile4 = (float4*)sm;      // 16384 floats, swizzled (64 KB)
    float*  s_p   = sm + 16384;       // 4096 floats (16 KB)
    float*  s_la  = sm + 20480;       // 4096 partial logits (16 KB, 16 slabs)
    float*  s_a   = sm + 24576;       // 256 softmax weights
    float*  s_c   = sm + 24832;       // 8
    float*  s_m   = sm + 24840;       // 32
    float*  s_am  = sm + 24872;       // 1

    const int i    = blockIdx.x;
    const int tid  = threadIdx.x;
    const int lane = tid & 31, w = tid >> 5;   // 16 warps

    // async-stage tile (swizzled) and p (linear); overlaps with c/mask work
    {
        const uint32_t tdst = smem_u32(sm);
        const float4* tg = (const float4*)(tgt + (size_t)i * (TT * DM));
        #pragma unroll
        for (int r = 0; r < 8; r++) {
            const int gg = tid + 512 * r;
            const int t = gg >> 7, k4 = gg & 127;
            CP_ASYNC16(tdst + (((t << 7) + (k4 ^ (t & 7))) << 4), tg + gg);
        }
        const uint32_t pdst = smem_u32(s_p);
        const float4* pg = (const float4*)P + (size_t)i * 1024;
        #pragma unroll
        for (int r = 0; r < 2; r++)
            CP_ASYNC16(pdst + ((tid + 512 * r) << 4), pg + tid + 512 * r);
        CP_COMMIT();
    }

    // c[h] = q_h . b_k_h (warps 0..7, head = w)
    if (w < 8) {
        const bf16* qh = Qh + (size_t)i * DM + w * DH;
        const bf16* ql = Ql + (size_t)i * DM + w * DH;
        const float* br = ipb + DM + w * DH;
        float q0 = __bfloat162float(qh[lane])      + __bfloat162float(ql[lane]);
        float q1 = __bfloat162float(qh[lane + 32]) + __bfloat162float(ql[lane + 32]);
        float cs = q0 * br[lane] + q1 * br[lane + 32];
        #pragma unroll
        for (int off = 16; off; off >>= 1)
            cs += __shfl_down_sync(0xffffffffu, cs, off);
        if (lane == 0) s_c[w] = cs;
    }
    if (w == 8) {
        const int mode = *mask_mode;
        unsigned mv;
        if (mode == 0)      mv = ((const unsigned char*)mask_raw)[(size_t)i * TT + lane];
        else if (mode == 1) mv = ((const unsigned*)mask_raw)[(size_t)i * TT + lane] != 0u;
        else                mv = ((const float*)mask_raw)[(size_t)i * TT + lane] != 0.f;
        s_m[lane] = mv ? 1.f : 0.f;
        unsigned bal = __ballot_sync(0xffffffffu, mv != 0);
        if (lane == 0) {
            int am = (bal == 0xffffffffu) ? 1 : 0;
            s_am[0] = (float)am;
            allm[i] = am;
        }
    }
    CP_WAIT0();
    __syncthreads();

    // logits partials: warp w = k-slab w (8 float4), lane = t, 8 heads
    {
        const int kb0 = w << 3;
        const int cx = lane & 7, tb = lane << 7;
        float s[NH] = {};
        #pragma unroll
        for (int j = 0; j < 8; j++) {
            const int k4 = kb0 + j;
            const float4 tv = tile4[tb + (k4 ^ cx)];
            #pragma unroll
            for (int h = 0; h < NH; h++) {
                const float4 pv = ((const float4*)(s_p + h * DM))[k4];
                s[h] += tv.x * pv.x + tv.y * pv.y + tv.z * pv.z + tv.w * pv.w;
            }
        }
        #pragma unroll
        for (int h = 0; h < NH; h++)
            s_la[(w << 8) + (h << 5) + lane] = s[h];
    }
    __syncthreads();

    // reduce + softmax (warps 0..7: head = w, lane = t)
    if (w < 8) {
        const float am = s_am[0];
        float l = s_c[w];
        #pragma unroll
        for (int j = 0; j < 16; j++) l += s_la[(j << 8) + (w << 5) + lane];
        const bool inv = (s_m[lane] != 0.f) && (am == 0.f);
        l = inv ? -1e30f : l * 0.125f;
        float m = l;
        #pragma unroll
        for (int off = 16; off; off >>= 1)
            m = fmaxf(m, __shfl_xor_sync(0xffffffffu, m, off));
        float e = inv ? 0.f : __expf(l - m);
        float s = e;
        #pragma unroll
        for (int off = 16; off; off >>= 1)
            s += __shfl_xor_sync(0xffffffffu, s, off);
        s_a[(w << 5) + lane] = e / s;
    }
    __syncthreads();

    // u[h][k4] = sum_t a[h][t] * tile[t][k4]; thread = (k4, head-pair)
    {
        const int k4 = tid & 127, hp = tid >> 7;   // hp 0..3 -> heads 2hp, 2hp+1
        float4 a0 = make_float4(0.f, 0.f, 0.f, 0.f), a1 = a0;
        const float* sa0 = s_a + ((hp << 1) << 5);
        const float* sa1 = sa0 + 32;
        #pragma unroll 8
        for (int t = 0; t < TT; t++) {
            const float4 tv = tile4[(t << 7) + (k4 ^ (t & 7))];
            const float w0 = sa0[t], w1 = sa1[t];
            a0.x += w0 * tv.x; a0.y += w0 * tv.y; a0.z += w0 * tv.z; a0.w += w0 * tv.w;
            a1.x += w1 * tv.x; a1.y += w1 * tv.y; a1.z += w1 * tv.z; a1.w += w1 * tv.w;
        }
        const size_t base = (size_t)i * (NH * DM) + (size_t)((hp << 1) << 9) + (k4 << 2);
        uint2 hh2, ll2;
        split4(a0, hh2, ll2);
        *(uint2*)&Uhi[base] = hh2; *(uint2*)&Ulo[base] = ll2;
        split4(a1, hh2, ll2);
        *(uint2*)&Uhi[base + 512] = hh2; *(uint2*)&Ulo[base + 512] = ll2;
    }
}

// ======================= launch ============================================
extern "C" void kernel_launch(void* const* d_in, const int* in_sizes, int n_in,
                              void* d_out, int out_size) {
    const float* src  = (const float*)d_in[0];
    const float* tgt  = (const float*)d_in[1];
    const void*  mask = d_in[2];
    const float* ipw  = (const float*)d_in[3];
    const float* ipb  = (const float*)d_in[4];
    const float* opw  = (const float*)d_in[5];
    const float* opb  = (const float*)d_in[6];
    float*       out  = (float*)d_out;

    float *P; int *AM, *MODE;
    bf16 *SRCh, *SRCl, *Qh, *Ql, *Uh, *Ul, *CTXh, *CTXl;
    bf16 *WQh, *WQl, *WKTh, *WKTl, *WVh, *WVl, *WOh, *WOl;
    cudaGetSymbolAddress((void**)&P,    g_P);
    cudaGetSymbolAddress((void**)&AM,   g_AM);
    cudaGetSymbolAddress((void**)&MODE, g_MaskMode);
    cudaGetSymbolAddress((void**)&SRCh, g_SRCh); cudaGetSymbolAddress((void**)&SRCl, g_SRCl);
    cudaGetSymbolAddress((void**)&Qh,   g_Qh);   cudaGetSymbolAddress((void**)&Ql,   g_Ql);
    cudaGetSymbolAddress((void**)&Uh,   g_Uh);   cudaGetSymbolAddress((void**)&Ul,   g_Ul);
    cudaGetSymbolAddress((void**)&CTXh, g_CTXh); cudaGetSymbolAddress((void**)&CTXl, g_CTXl);
    cudaGetSymbolAddress((void**)&WQh,  g_WQh);  cudaGetSymbolAddress((void**)&WQl,  g_WQl);
    cudaGetSymbolAddress((void**)&WKTh, g_WKTh); cudaGetSymbolAddress((void**)&WKTl, g_WKTl);
    cudaGetSymbolAddress((void**)&WVh,  g_WVh);  cudaGetSymbolAddress((void**)&WVl,  g_WVl);
    cudaGetSymbolAddress((void**)&WOh,  g_WOh);  cudaGetSymbolAddress((void**)&WOl,  g_WOl);

    const int SMG64  = 3 * 20480;   // 60 KB, MT=64 3-stage
    const int SMG128 = 3 * 30720;   // 90 KB, MT=128 3-stage
    cudaFuncSetAttribute(hmma_gemm<64, 2, false>,  cudaFuncAttributeMaxDynamicSharedMemorySize, SMG64);
    cudaFuncSetAttribute(hmma_gemm<128, 1, false>, cudaFuncAttributeMaxDynamicSharedMemorySize, SMG128);
    cudaFuncSetAttribute(hmma_gemm<64, 1, true>,   cudaFuncAttributeMaxDynamicSharedMemorySize, SMG64);

    // 0) all prep in one launch
    prep_all<<<2049, 256>>>(src, ipw, opw, mask,
                            SRCh, SRCl, WQh, WQl, WVh, WVl, WOh, WOl,
                            WKTh, WKTl, MODE);

    // 1) Q = src @ Wq^T + bq  -> bf16 Qh/Ql only
    hmma_gemm<64, 2, false><<<dim3(32, 8, 1), 256, SMG64>>>(
        SRCh, SRCl, 512, 0, WQh, WQl, 512, 0,
        nullptr, Qh, Ql, 512, 0, ipb, 0, 512, nullptr);

    // 2) P = Q_h @ WkT_h^T  -> fp32 linear [i][h][512]
    hmma_gemm<128, 1, false><<<dim3(16, 8, 8), 256, SMG128>>>(
        Qh, Ql, 512, 64, WKTh, WKTl, 64, 512 * 64,
        P, nullptr, nullptr, 4096, 512, nullptr, 0, 64, nullptr);

    // 3) fused attention: logits -> softmax -> U (bf16 hi/lo direct)
    const int smemA = 24873 * 4;   // ~97 KB -> 2 CTAs/SM, 512 threads
    cudaFuncSetAttribute(attn_core, cudaFuncAttributeMaxDynamicSharedMemorySize, smemA);
    attn_core<<<2048, 512, smemA>>>(tgt, Qh, Ql, P, mask, MODE, ipb, Uh, Ul, AM);

    // 4) ctx_h = U_h @ Wv_h^T + bv  -> bf16 CTXh/CTXl
    hmma_gemm<64, 2, false><<<dim3(32, 1, 8), 256, SMG64>>>(
        Uh, Ul, 4096, 512, WVh, WVl, 512, 64 * 512,
        nullptr, CTXh, CTXl, 512, 64, ipb + 1024, 64, 512, nullptr);

    // 5) out = ctx @ Wo^T + bo, zeroing all-masked rows
    hmma_gemm<64, 1, true><<<dim3(32, 8, 1), 256, SMG64>>>(
        CTXh, CTXl, 512, 0, WOh, WOl, 512, 0,
        out, nullptr, nullptr, 512, 0, opb, 0, 512, AM);
}

// round 14
// speedup vs baseline: 1.0246x; 1.0246x over previous
#include <cuda_runtime.h>
#include <cuda_bf16.h>
#include <cstdint>

// Problem constants
#define NPOS 2048   // B*S
#define DM   512
#define NH   8
#define DH   64
#define TT   32

typedef __nv_bfloat16 bf16;

// Scratch (device globals)
__device__ float g_P  [NPOS * NH * DM];   // linear: [i][h][512]
__device__ int   g_AM [NPOS];
__device__ int   g_MaskMode;
__device__ __align__(16) bf16 g_SRCh[NPOS * DM],      g_SRCl[NPOS * DM];
__device__ __align__(16) bf16 g_Qh  [NPOS * DM],      g_Ql  [NPOS * DM];
__device__ __align__(16) bf16 g_Uh  [NPOS * NH * DM], g_Ul  [NPOS * NH * DM];
__device__ __align__(16) bf16 g_CTXh[NPOS * DM],      g_CTXl[NPOS * DM];
__device__ __align__(16) bf16 g_WQh [DM * DM],        g_WQl [DM * DM];
__device__ __align__(16) bf16 g_WKTh[NH * DM * DH],   g_WKTl[NH * DM * DH];
__device__ __align__(16) bf16 g_WVh [DM * DM],        g_WVl [DM * DM];
__device__ __align__(16) bf16 g_WOh [DM * DM],        g_WOl [DM * DM];

// ======================= helpers ===========================================
__device__ __forceinline__ uint32_t smem_u32(const void* p) {
    uint32_t a;
    asm("{ .reg .u64 t; cvta.to.shared.u64 t, %1; cvt.u32.u64 %0, t; }"
        : "=r"(a) : "l"(p));
    return a;
}
__device__ __forceinline__ void ldm_x4(uint32_t* r, uint32_t addr) {
    asm volatile("ldmatrix.sync.aligned.m8n8.x4.shared.b16 {%0,%1,%2,%3}, [%4];"
                 : "=r"(r[0]), "=r"(r[1]), "=r"(r[2]), "=r"(r[3]) : "r"(addr));
}
__device__ __forceinline__ void mma_bf16(float* d, const uint32_t* a,
                                         uint32_t b0, uint32_t b1) {
    asm volatile(
        "mma.sync.aligned.m16n8k16.row.col.f32.bf16.bf16.f32 "
        "{%0,%1,%2,%3}, {%4,%5,%6,%7}, {%8,%9}, {%0,%1,%2,%3};"
        : "+f"(d[0]), "+f"(d[1]), "+f"(d[2]), "+f"(d[3])
        : "r"(a[0]), "r"(a[1]), "r"(a[2]), "r"(a[3]), "r"(b0), "r"(b1));
}
#define CP_ASYNC16(dst, src) \
    asm volatile("cp.async.cg.shared.global [%0], [%1], 16;" \
                 :: "r"(dst), "l"(src) : "memory")
#define CP_COMMIT() asm volatile("cp.async.commit_group;" ::: "memory")
#define CP_WAIT1()  asm volatile("cp.async.wait_group 1;" ::: "memory")
#define CP_WAIT0()  asm volatile("cp.async.wait_group 0;" ::: "memory")

__device__ __forceinline__ unsigned pack_bf2(bf16 a, bf16 b) {
    __nv_bfloat162 t; t.x = a; t.y = b;
    return *reinterpret_cast<unsigned*>(&t);
}
__device__ __forceinline__ void split4(float4 v, uint2& hi, uint2& lo) {
    bf16 hx = __float2bfloat16(v.x), hy = __float2bfloat16(v.y);
    bf16 hz = __float2bfloat16(v.z), hw = __float2bfloat16(v.w);
    bf16 lx = __float2bfloat16(v.x - __bfloat162float(hx));
    bf16 ly = __float2bfloat16(v.y - __bfloat162float(hy));
    bf16 lz = __float2bfloat16(v.z - __bfloat162float(hz));
    bf16 lw = __float2bfloat16(v.w - __bfloat162float(hw));
    hi = make_uint2(pack_bf2(hx, hy), pack_bf2(hz, hw));
    lo = make_uint2(pack_bf2(lx, ly), pack_bf2(lz, lw));
}
__device__ __forceinline__ void split2_store(float x, float y,
                                             bf16* hi, bf16* lo, size_t off) {
    bf16 hx = __float2bfloat16(x), hy = __float2bfloat16(y);
    bf16 lx = __float2bfloat16(x - __bfloat162float(hx));
    bf16 ly = __float2bfloat16(y - __bfloat162float(hy));
    *(uint32_t*)&hi[off] = pack_bf2(hx, hy);
    *(uint32_t*)&lo[off] = pack_bf2(lx, ly);
}

// ======================= fused prep kernel =================================
__global__ __launch_bounds__(256) void prep_all(
    const float* __restrict__ src, const float* __restrict__ ipw,
    const float* __restrict__ opw, const void* __restrict__ mask,
    bf16* __restrict__ SRCh, bf16* __restrict__ SRCl,
    bf16* __restrict__ WQh,  bf16* __restrict__ WQl,
    bf16* __restrict__ WVh,  bf16* __restrict__ WVl,
    bf16* __restrict__ WOh,  bf16* __restrict__ WOl,
    bf16* __restrict__ WKTh, bf16* __restrict__ WKTl,
    int* __restrict__ mode)
{
    const int b = blockIdx.x, tid = threadIdx.x;
    if (b < 1792) {
        const float* x; bf16 *hi, *lo; int i;
        if (b < 1024)      { x = src;             hi = SRCh; lo = SRCl; i = b * 256 + tid; }
        else if (b < 1280) { x = ipw;             hi = WQh;  lo = WQl;  i = (b - 1024) * 256 + tid; }
        else if (b < 1536) { x = ipw + 1024*512;  hi = WVh;  lo = WVl;  i = (b - 1280) * 256 + tid; }
        else               { x = opw;             hi = WOh;  lo = WOl;  i = (b - 1536) * 256 + tid; }
        float4 v = ((const float4*)x)[i];
        uint2 h, l; split4(v, h, l);
        ((uint2*)hi)[i] = h; ((uint2*)lo)[i] = l;
    } else if (b < 2048) {
        __shared__ float t[32][33];
        const int r = b - 1792;
        const int h = r >> 5, nb = (r & 15) * 32, kb = ((r >> 4) & 1) * 32;
        const int x = tid & 31, y = tid >> 5;
        for (int i = y; i < 32; i += 8)
            t[i][x] = ipw[(size_t)(512 + h * 64 + kb + i) * 512 + nb + x];
        __syncthreads();
        for (int i = y; i < 32; i += 8) {
            float v = t[x][i];
            size_t o = (size_t)h * (512 * 64) + (size_t)(nb + i) * 64 + kb + x;
            bf16 bh = __float2bfloat16(v);
            WKTh[o] = bh;
            WKTl[o] = __float2bfloat16(v - __bfloat162float(bh));
        }
    } else {
        __shared__ int flags[2];
        if (tid < 2) flags[tid] = 0;
        __syncthreads();
        const unsigned* w = (const unsigned*)mask;
        for (int j = tid; j < 16384; j += 256) {
            unsigned v = w[j];
            if (v == 0x3F800000u) atomicOr(&flags[0], 1);
            else if (v > 1u)      atomicOr(&flags[1], 1);
        }
        __syncthreads();
        if (tid == 0) *mode = flags[0] ? 2 : (flags[1] ? 0 : 1);
    }
}

// ======================= HMMA GEMM (cp.async, MT x 64 tile, BK param) ======
// C[M,N] = A[M,K] @ B[N,K]^T + bias; pre-split bf16 hi/lo planes; split
// product hi*hi + hi*lo + lo*hi. MT=128: 4Mx2N warps; MT=64: 2Mx4N warps.
// BK = k-depth per pipeline stage (32 or 64). Row stride 2*BK+16 bytes keeps
// ldmatrix conflict-free. EMIT bit0: fp32 C; bit1: bf16 hi/lo planes.
template <int MT, int BK, int EMIT, bool ZMASK>
__global__ __launch_bounds__(256, 2) void hmma_gemm(
    const bf16* __restrict__ Ahi, const bf16* __restrict__ Alo, int lda, int aoz,
    const bf16* __restrict__ Bhi, const bf16* __restrict__ Blo, int ldb, int boz,
    float* __restrict__ C, bf16* __restrict__ Chi, bf16* __restrict__ Clo,
    int ldc, int coz,
    const float* __restrict__ bias, int bioz,
    int K, const int* __restrict__ rmask)
{
    constexpr int RS  = 2 * BK + 16;        // 80 (BK=32) or 144 (BK=64)
    constexpr int APL = MT * RS;
    constexpr int BPL = 64 * RS;
    constexpr int STG = 2 * APL + 2 * BPL;
    constexpr int NTW = (MT == 128) ? 32 : 16;
    constexpr int NT8 = NTW / 8;
    constexpr int CPR = BK / 8;             // 16B chunks per row

    extern __shared__ char smem[];
    const uint32_t sbase = smem_u32(smem);

    const int z = blockIdx.z;
    Ahi += (size_t)z * aoz;  Alo += (size_t)z * aoz;
    Bhi += (size_t)z * boz;  Blo += (size_t)z * boz;
    const int m0 = blockIdx.x * MT, n0 = blockIdx.y * 64;

    const int tid = threadIdx.x, lane = tid & 31, wid = tid >> 5;
    const int wm = (MT == 128) ? (wid & 3) : (wid & 1);
    const int wn = (MT == 128) ? (wid >> 2) : (wid >> 1);

    const int g = lane >> 3, lr = lane & 7;
    const int grow = (g & 1) * 8 + lr;
    const int gk   = (g >> 1) * 16;

    float acc[2][NT8][4] = {};
    const int nst = K / BK;

    auto issue = [&](int s) {
        const int kt = s * BK;
        const uint32_t sb = sbase + (s % 3) * STG;
        #pragma unroll
        for (int r = 0; r < (MT * CPR) / 256; r++) {
            const int c = tid + 256 * r;
            const int row = c / CPR, col = c % CPR;
            CP_ASYNC16(sb + row * RS + col * 16,
                       &Ahi[(size_t)(m0 + row) * lda + kt + col * 8]);
            CP_ASYNC16(sb + APL + row * RS + col * 16,
                       &Alo[(size_t)(m0 + row) * lda + kt + col * 8]);
        }
        #pragma unroll
        for (int r = 0; r < (64 * CPR) / 256; r++) {
            const int c = tid + 256 * r;
            const int row = c / CPR, col = c % CPR;
            CP_ASYNC16(sb + 2 * APL + row * RS + col * 16,
                       &Bhi[(size_t)(n0 + row) * ldb + kt + col * 8]);
            CP_ASYNC16(sb + 2 * APL + BPL + row * RS + col * 16,
                       &Blo[(size_t)(n0 + row) * ldb + kt + col * 8]);
        }
    };

    issue(0); CP_COMMIT();
    if (nst > 1) issue(1);
    CP_COMMIT();

    for (int s = 0; s < nst; s++) {
        CP_WAIT1();
        __syncthreads();
        if (s + 2 < nst) issue(s + 2);
        CP_COMMIT();

        const uint32_t sb = sbase + (s % 3) * STG;
        const uint32_t ahs = sb, als = sb + APL;
        const uint32_t bhs = sb + 2 * APL, bls = bhs + BPL;
        #pragma unroll
        for (int kk = 0; kk < BK / 16; kk++) {
            const int kb = kk * 32 + gk;
            uint32_t a_hi[2][4], a_lo[2][4], b_hi[NT8 / 2][4], b_lo[NT8 / 2][4];
            #pragma unroll
            for (int mt = 0; mt < 2; mt++) {
                const uint32_t ro = (wm * 32 + mt * 16 + grow) * RS + kb;
                ldm_x4(a_hi[mt], ahs + ro);
                ldm_x4(a_lo[mt], als + ro);
            }
            #pragma unroll
            for (int ng = 0; ng < NT8 / 2; ng++) {
                const uint32_t ro = (wn * NTW + ng * 16 + grow) * RS + kb;
                ldm_x4(b_hi[ng], bhs + ro);
                ldm_x4(b_lo[ng], bls + ro);
            }
            #pragma unroll
            for (int mt = 0; mt < 2; mt++)
                #pragma unroll
                for (int nt = 0; nt < NT8; nt++) {
                    const int ng = nt >> 1, sel = nt & 1;
                    const uint32_t bh0 = b_hi[ng][sel], bh1 = b_hi[ng][sel + 2];
                    const uint32_t bl0 = b_lo[ng][sel], bl1 = b_lo[ng][sel + 2];
                    mma_bf16(acc[mt][nt], a_hi[mt], bh0, bh1);
                    mma_bf16(acc[mt][nt], a_hi[mt], bl0, bl1);
                    mma_bf16(acc[mt][nt], a_lo[mt], bh0, bh1);
                }
        }
    }

    // epilogue
    const int qr = lane >> 2, qc = (lane & 3) * 2;
    #pragma unroll
    for (int mt = 0; mt < 2; mt++) {
        const int r0 = m0 + wm * 32 + mt * 16 + qr;
        const bool z0 = ZMASK ? (rmask[r0] != 0)     : false;
        const bool z1 = ZMASK ? (rmask[r0 + 8] != 0) : false;
        #pragma unroll
        for (int nt = 0; nt < NT8; nt++) {
            const int c = n0 + wn * NTW + nt * 8 + qc;
            float b0 = 0.f, b1 = 0.f;
            if (bias) { b0 = bias[(size_t)z * bioz + c]; b1 = bias[(size_t)z * bioz + c + 1]; }
            float2 v0 = make_float2(acc[mt][nt][0] + b0, acc[mt][nt][1] + b1);
            float2 v1 = make_float2(acc[mt][nt][2] + b0, acc[mt][nt][3] + b1);
            if (z0) v0 = make_float2(0.f, 0.f);
            if (z1) v1 = make_float2(0.f, 0.f);
            const size_t o0 = (size_t)z * coz + (size_t)r0 * ldc + c;
            const size_t o1 = o0 + (size_t)8 * ldc;
            if (EMIT & 1) { *(float2*)&C[o0] = v0; *(float2*)&C[o1] = v1; }
            if (EMIT & 2) {
                split2_store(v0.x, v0.y, Chi, Clo, o0);
                split2_store(v1.x, v1.y, Chi, Clo, o1);
            }
        }
    }
}

// ======================= fused attention core (v5, R12 — proven 54.7us) ====
__global__ __launch_bounds__(256, 2) void attn_core(
    const float* __restrict__ tgt,
    const bf16* __restrict__ Qh, const bf16* __restrict__ Ql,
    const float* __restrict__ P,
    const void* __restrict__ mask_raw,
    const int* __restrict__ mask_mode,
    const float* __restrict__ ipb,
    bf16* __restrict__ Uhi, bf16* __restrict__ Ulo,
    int* __restrict__ allm)
{
    extern __shared__ float sm[];
    float4* tile4 = (float4*)sm;      // 16384 floats, swizzled (64 KB)
    float*  s_p   = sm + 16384;       // 4096 floats (16 KB)
    float*  s_la  = sm + 20480;       // 2048 partial logits (8 KB)
    float*  s_a   = sm + 22528;       // 256 softmax weights
    float*  s_c   = sm + 22784;       // 8
    float*  s_m   = sm + 22792;       // 32
    float*  s_am  = sm + 22824;       // 1

    const int i    = blockIdx.x;
    const int tid  = threadIdx.x;
    const int lane = tid & 31, w = tid >> 5;

    // async-stage tile (swizzled) and p (linear) — overlaps with c/mask below
    {
        const uint32_t tdst = smem_u32(sm);
        const float4* tg = (const float4*)(tgt + (size_t)i * (TT * DM));
        #pragma unroll
        for (int r = 0; r < 16; r++) {
            const int gg = tid + 256 * r;
            const int t = gg >> 7, k4 = gg & 127;
            CP_ASYNC16(tdst + (((t << 7) + (k4 ^ (t & 7))) << 4), tg + gg);
        }
        const uint32_t pdst = smem_u32(s_p);
        const float4* pg = (const float4*)P + (size_t)i * 1024;
        #pragma unroll
        for (int r = 0; r < 4; r++)
            CP_ASYNC16(pdst + ((tid + 256 * r) << 4), pg + tid + 256 * r);
        CP_COMMIT();
    }

    // c[h] = q_h . b_k_h (q reconstructed hi+lo)
    {
        const bf16* qh = Qh + (size_t)i * DM + w * DH;
        const bf16* ql = Ql + (size_t)i * DM + w * DH;
        const float* br = ipb + DM + w * DH;
        float q0 = __bfloat162float(qh[lane])      + __bfloat162float(ql[lane]);
        float q1 = __bfloat162float(qh[lane + 32]) + __bfloat162float(ql[lane + 32]);
        float cs = q0 * br[lane] + q1 * br[lane + 32];
        #pragma unroll
        for (int off = 16; off; off >>= 1)
            cs += __shfl_down_sync(0xffffffffu, cs, off);
        if (lane == 0) s_c[w] = cs;
    }
    if (w == 0) {
        const int mode = *mask_mode;
        unsigned mv;
        if (mode == 0)      mv = ((const unsigned char*)mask_raw)[(size_t)i * TT + lane];
        else if (mode == 1) mv = ((const unsigned*)mask_raw)[(size_t)i * TT + lane] != 0u;
        else                mv = ((const float*)mask_raw)[(size_t)i * TT + lane] != 0.f;
        s_m[lane] = mv ? 1.f : 0.f;
        unsigned bal = __ballot_sync(0xffffffffu, mv != 0);
        if (lane == 0) {
            int am = (bal == 0xffffffffu) ? 1 : 0;
            s_am[0] = (float)am;
            allm[i] = am;
        }
    }
    CP_WAIT0();
    __syncthreads();

    // logits partials: warp w = k-slab w (16 float4), lane = t, 8 heads
    {
        const int kb0 = w << 4;
        const int cx = lane & 7, tb = lane << 7;
        float s[NH] = {};
        #pragma unroll
        for (int j = 0; j < 16; j++) {
            const int k4 = kb0 + j;
            const float4 tv = tile4[tb + (k4 ^ cx)];
            #pragma unroll
            for (int h = 0; h < NH; h++) {
                const float4 pv = ((const float4*)(s_p + h * DM))[k4];
                s[h] += tv.x * pv.x + tv.y * pv.y + tv.z * pv.z + tv.w * pv.w;
            }
        }
        #pragma unroll
        for (int h = 0; h < NH; h++)
            s_la[(w << 8) + (h << 5) + lane] = s[h];
    }
    __syncthreads();

    // reduce + softmax (warp w = head w, lane = t)
    {
        const float am = s_am[0];
        float l = s_c[w];
        #pragma unroll
        for (int j = 0; j < 8; j++) l += s_la[(j << 8) + (w << 5) + lane];
        const bool inv = (s_m[lane] != 0.f) && (am == 0.f);
        l = inv ? -1e30f : l * 0.125f;
        float m = l;
        #pragma unroll
        for (int off = 16; off; off >>= 1)
            m = fmaxf(m, __shfl_xor_sync(0xffffffffu, m, off));
        float e = inv ? 0.f : __expf(l - m);
        float s = e;
        #pragma unroll
        for (int off = 16; off; off >>= 1)
            s += __shfl_xor_sync(0xffffffffu, s, off);
        s_a[(w << 5) + lane] = e / s;
    }
    __syncthreads();

    // u[h][k4] = sum_t a[h][t] * tile[t][k4]; thread = (k4, head-half)
    {
        const int k4 = tid & 127, hh = tid >> 7;
        float4 acc[4];
        #pragma unroll
        for (int h = 0; h < 4; h++) acc[h] = make_float4(0.f, 0.f, 0.f, 0.f);
        #pragma unroll 8
        for (int t = 0; t < TT; t++) {
            const float4 tv = tile4[(t << 7) + (k4 ^ (t & 7))];
            #pragma unroll
            for (int h = 0; h < 4; h++) {
                const float a = s_a[(((hh << 2) + h) << 5) + t];
                acc[h].x += a * tv.x; acc[h].y += a * tv.y;
                acc[h].z += a * tv.z; acc[h].w += a * tv.w;
            }
        }
        const size_t base = (size_t)i * (NH * DM);
        #pragma unroll
        for (int h = 0; h < 4; h++) {
            uint2 hh2, ll2; split4(acc[h], hh2, ll2);
            const size_t o = base + (size_t)(((hh << 2) + h) << 9) + (k4 << 2);
            *(uint2*)&Uhi[o] = hh2;
            *(uint2*)&Ulo[o] = ll2;
        }
    }
}

// ======================= launch ============================================
extern "C" void kernel_launch(void* const* d_in, const int* in_sizes, int n_in,
                              void* d_out, int out_size) {
    const float* src  = (const float*)d_in[0];
    const float* tgt  = (const float*)d_in[1];
    const void*  mask = d_in[2];
    const float* ipw  = (const float*)d_in[3];
    const float* ipb  = (const float*)d_in[4];
    const float* opw  = (const float*)d_in[5];
    const float* opb  = (const float*)d_in[6];
    float*       out  = (float*)d_out;

    float *P; int *AM, *MODE;
    bf16 *SRCh, *SRCl, *Qh, *Ql, *Uh, *Ul, *CTXh, *CTXl;
    bf16 *WQh, *WQl, *WKTh, *WKTl, *WVh, *WVl, *WOh, *WOl;
    cudaGetSymbolAddress((void**)&P,    g_P);
    cudaGetSymbolAddress((void**)&AM,   g_AM);
    cudaGetSymbolAddress((void**)&MODE, g_MaskMode);
    cudaGetSymbolAddress((void**)&SRCh, g_SRCh); cudaGetSymbolAddress((void**)&SRCl, g_SRCl);
    cudaGetSymbolAddress((void**)&Qh,   g_Qh);   cudaGetSymbolAddress((void**)&Ql,   g_Ql);
    cudaGetSymbolAddress((void**)&Uh,   g_Uh);   cudaGetSymbolAddress((void**)&Ul,   g_Ul);
    cudaGetSymbolAddress((void**)&CTXh, g_CTXh); cudaGetSymbolAddress((void**)&CTXl, g_CTXl);
    cudaGetSymbolAddress((void**)&WQh,  g_WQh);  cudaGetSymbolAddress((void**)&WQl,  g_WQl);
    cudaGetSymbolAddress((void**)&WKTh, g_WKTh); cudaGetSymbolAddress((void**)&WKTl, g_WKTl);
    cudaGetSymbolAddress((void**)&WVh,  g_WVh);  cudaGetSymbolAddress((void**)&WVl,  g_WVl);
    cudaGetSymbolAddress((void**)&WOh,  g_WOh);  cudaGetSymbolAddress((void**)&WOl,  g_WOl);

    const int SMG64  = 3 * (2 * 64 * 144 + 2 * 64 * 144);   // 110.6 KB, MT=64 BK=64
    const int SMG128 = 3 * (2 * 128 * 80 + 2 * 64 * 80);    // 90 KB,   MT=128 BK=32
    cudaFuncSetAttribute((const void*)hmma_gemm<64, 64, 2, false>,
                         cudaFuncAttributeMaxDynamicSharedMemorySize, SMG64);
    cudaFuncSetAttribute((const void*)hmma_gemm<128, 32, 1, false>,
                         cudaFuncAttributeMaxDynamicSharedMemorySize, SMG128);
    cudaFuncSetAttribute((const void*)hmma_gemm<64, 64, 1, true>,
                         cudaFuncAttributeMaxDynamicSharedMemorySize, SMG64);

    // 0) all prep in one launch
    prep_all<<<2049, 256>>>(src, ipw, opw, mask,
                            SRCh, SRCl, WQh, WQl, WVh, WVl, WOh, WOl,
                            WKTh, WKTl, MODE);

    // 1) Q = src @ Wq^T + bq  -> bf16 Qh/Ql only
    hmma_gemm<64, 64, 2, false><<<dim3(32, 8, 1), 256, SMG64>>>(
        SRCh, SRCl, 512, 0, WQh, WQl, 512, 0,
        nullptr, Qh, Ql, 512, 0, ipb, 0, 512, nullptr);

    // 2) P = Q_h @ WkT_h^T  -> fp32 linear [i][h][512]   (K=64, BK=32)
    hmma_gemm<128, 32, 1, false><<<dim3(16, 8, 8), 256, SMG128>>>(
        Qh, Ql, 512, 64, WKTh, WKTl, 64, 512 * 64,
        P, nullptr, nullptr, 4096, 512, nullptr, 0, 64, nullptr);

    // 3) fused attention: logits -> softmax -> U (bf16 hi/lo direct)
    const int smemA = 22825 * 4;   // ~91 KB -> 2 CTAs/SM
    cudaFuncSetAttribute(attn_core, cudaFuncAttributeMaxDynamicSharedMemorySize, smemA);
    attn_core<<<2048, 256, smemA>>>(tgt, Qh, Ql, P, mask, MODE, ipb, Uh, Ul, AM);

    // 4) ctx_h = U_h @ Wv_h^T + bv  -> bf16 CTXh/CTXl
    hmma_gemm<64, 64, 2, false><<<dim3(32, 1, 8), 256, SMG64>>>(
        Uh, Ul, 4096, 512, WVh, WVl, 512, 64 * 512,
        nullptr, CTXh, CTXl, 512, 64, ipb + 1024, 64, 512, nullptr);

    // 5) out = ctx @ Wo^T + bo, zeroing all-masked rows
    hmma_gemm<64, 64, 1, true><<<dim3(32, 8, 1), 256, SMG64>>>(
        CTXh, CTXl, 512, 0, WOh, WOl, 512, 0,
        out, nullptr, nullptr, 512, 0, opb, 0, 512, AM);
}

// round 15
// speedup vs baseline: 1.0259x; 1.0012x over previous
#include <cuda_runtime.h>
#include <cuda_bf16.h>
#include <cstdint>

// Problem constants
#define NPOS 2048   // B*S
#define DM   512
#define NH   8
#define DH   64
#define TT   32

typedef __nv_bfloat16 bf16;

// Scratch (device globals)
__device__ float g_P  [NPOS * NH * DM];   // linear: [i][h][512]
__device__ int   g_AM [NPOS];
__device__ int   g_MaskMode;
__device__ __align__(16) bf16 g_SRCh[NPOS * DM],      g_SRCl[NPOS * DM];
__device__ __align__(16) bf16 g_Qh  [NPOS * DM],      g_Ql  [NPOS * DM];
__device__ __align__(16) bf16 g_Uh  [NPOS * NH * DM], g_Ul  [NPOS * NH * DM];
__device__ __align__(16) bf16 g_CTXh[NPOS * DM],      g_CTXl[NPOS * DM];
__device__ __align__(16) bf16 g_WQh [DM * DM],        g_WQl [DM * DM];
__device__ __align__(16) bf16 g_WKTh[NH * DM * DH],   g_WKTl[NH * DM * DH];
__device__ __align__(16) bf16 g_WVh [DM * DM],        g_WVl [DM * DM];
__device__ __align__(16) bf16 g_WOh [DM * DM],        g_WOl [DM * DM];

// ======================= helpers ===========================================
__device__ __forceinline__ uint32_t smem_u32(const void* p) {
    uint32_t a;
    asm("{ .reg .u64 t; cvta.to.shared.u64 t, %1; cvt.u32.u64 %0, t; }"
        : "=r"(a) : "l"(p));
    return a;
}
__device__ __forceinline__ void ldm_x4(uint32_t* r, uint32_t addr) {
    asm volatile("ldmatrix.sync.aligned.m8n8.x4.shared.b16 {%0,%1,%2,%3}, [%4];"
                 : "=r"(r[0]), "=r"(r[1]), "=r"(r[2]), "=r"(r[3]) : "r"(addr));
}
__device__ __forceinline__ void mma_bf16(float* d, const uint32_t* a,
                                         uint32_t b0, uint32_t b1) {
    asm volatile(
        "mma.sync.aligned.m16n8k16.row.col.f32.bf16.bf16.f32 "
        "{%0,%1,%2,%3}, {%4,%5,%6,%7}, {%8,%9}, {%0,%1,%2,%3};"
        : "+f"(d[0]), "+f"(d[1]), "+f"(d[2]), "+f"(d[3])
        : "r"(a[0]), "r"(a[1]), "r"(a[2]), "r"(a[3]), "r"(b0), "r"(b1));
}
#define CP_ASYNC16(dst, src) \
    asm volatile("cp.async.cg.shared.global [%0], [%1], 16;" \
                 :: "r"(dst), "l"(src) : "memory")
#define CP_COMMIT() asm volatile("cp.async.commit_group;" ::: "memory")
#define CP_WAIT1()  asm volatile("cp.async.wait_group 1;" ::: "memory")
#define CP_WAIT0()  asm volatile("cp.async.wait_group 0;" ::: "memory")

__device__ __forceinline__ unsigned pack_bf2(bf16 a, bf16 b) {
    __nv_bfloat162 t; t.x = a; t.y = b;
    return *reinterpret_cast<unsigned*>(&t);
}
__device__ __forceinline__ void split4(float4 v, uint2& hi, uint2& lo) {
    bf16 hx = __float2bfloat16(v.x), hy = __float2bfloat16(v.y);
    bf16 hz = __float2bfloat16(v.z), hw = __float2bfloat16(v.w);
    bf16 lx = __float2bfloat16(v.x - __bfloat162float(hx));
    bf16 ly = __float2bfloat16(v.y - __bfloat162float(hy));
    bf16 lz = __float2bfloat16(v.z - __bfloat162float(hz));
    bf16 lw = __float2bfloat16(v.w - __bfloat162float(hw));
    hi = make_uint2(pack_bf2(hx, hy), pack_bf2(hz, hw));
    lo = make_uint2(pack_bf2(lx, ly), pack_bf2(lz, lw));
}
__device__ __forceinline__ void split2_store(float x, float y,
                                             bf16* hi, bf16* lo, size_t off) {
    bf16 hx = __float2bfloat16(x), hy = __float2bfloat16(y);
    bf16 lx = __float2bfloat16(x - __bfloat162float(hx));
    bf16 ly = __float2bfloat16(y - __bfloat162float(hy));
    *(uint32_t*)&hi[off] = pack_bf2(hx, hy);
    *(uint32_t*)&lo[off] = pack_bf2(lx, ly);
}

// ======================= fused prep kernel =================================
__global__ __launch_bounds__(256) void prep_all(
    const float* __restrict__ src, const float* __restrict__ ipw,
    const float* __restrict__ opw, const void* __restrict__ mask,
    bf16* __restrict__ SRCh, bf16* __restrict__ SRCl,
    bf16* __restrict__ WQh,  bf16* __restrict__ WQl,
    bf16* __restrict__ WVh,  bf16* __restrict__ WVl,
    bf16* __restrict__ WOh,  bf16* __restrict__ WOl,
    bf16* __restrict__ WKTh, bf16* __restrict__ WKTl,
    int* __restrict__ mode)
{
    const int b = blockIdx.x, tid = threadIdx.x;
    if (b < 1792) {
        const float* x; bf16 *hi, *lo; int i;
        if (b < 1024)      { x = src;             hi = SRCh; lo = SRCl; i = b * 256 + tid; }
        else if (b < 1280) { x = ipw;             hi = WQh;  lo = WQl;  i = (b - 1024) * 256 + tid; }
        else if (b < 1536) { x = ipw + 1024*512;  hi = WVh;  lo = WVl;  i = (b - 1280) * 256 + tid; }
        else               { x = opw;             hi = WOh;  lo = WOl;  i = (b - 1536) * 256 + tid; }
        float4 v = ((const float4*)x)[i];
        uint2 h, l; split4(v, h, l);
        ((uint2*)hi)[i] = h; ((uint2*)lo)[i] = l;
    } else if (b < 2048) {
        __shared__ float t[32][33];
        const int r = b - 1792;
        const int h = r >> 5, nb = (r & 15) * 32, kb = ((r >> 4) & 1) * 32;
        const int x = tid & 31, y = tid >> 5;
        for (int i = y; i < 32; i += 8)
            t[i][x] = ipw[(size_t)(512 + h * 64 + kb + i) * 512 + nb + x];
        __syncthreads();
        for (int i = y; i < 32; i += 8) {
            float v = t[x][i];
            size_t o = (size_t)h * (512 * 64) + (size_t)(nb + i) * 64 + kb + x;
            bf16 bh = __float2bfloat16(v);
            WKTh[o] = bh;
            WKTl[o] = __float2bfloat16(v - __bfloat162float(bh));
        }
    } else {
        __shared__ int flags[2];
        if (tid < 2) flags[tid] = 0;
        __syncthreads();
        const unsigned* w = (const unsigned*)mask;
        for (int j = tid; j < 16384; j += 256) {
            unsigned v = w[j];
            if (v == 0x3F800000u) atomicOr(&flags[0], 1);
            else if (v > 1u)      atomicOr(&flags[1], 1);
        }
        __syncthreads();
        if (tid == 0) *mode = flags[0] ? 2 : (flags[1] ? 0 : 1);
    }
}

// ======================= HMMA GEMM (cp.async, MT x 64 tile, BK param) ======
// C[M,N] = A[M,K] @ B[N,K]^T + bias; pre-split bf16 hi/lo planes; split
// product hi*hi + hi*lo + lo*hi. MT=128: 4Mx2N warps; MT=64: 2Mx4N warps.
// BK = k-depth per pipeline stage (32 or 64). Row stride 2*BK+16 bytes keeps
// ldmatrix conflict-free. EMIT bit0: fp32 C; bit1: bf16 hi/lo planes.
template <int MT, int BK, int EMIT, bool ZMASK>
__global__ __launch_bounds__(256, 2) void hmma_gemm(
    const bf16* __restrict__ Ahi, const bf16* __restrict__ Alo, int lda, int aoz,
    const bf16* __restrict__ Bhi, const bf16* __restrict__ Blo, int ldb, int boz,
    float* __restrict__ C, bf16* __restrict__ Chi, bf16* __restrict__ Clo,
    int ldc, int coz,
    const float* __restrict__ bias, int bioz,
    int K, const int* __restrict__ rmask)
{
    constexpr int RS  = 2 * BK + 16;        // 80 (BK=32) or 144 (BK=64)
    constexpr int APL = MT * RS;
    constexpr int BPL = 64 * RS;
    constexpr int STG = 2 * APL + 2 * BPL;
    constexpr int NTW = (MT == 128) ? 32 : 16;
    constexpr int NT8 = NTW / 8;
    constexpr int CPR = BK / 8;             // 16B chunks per row

    extern __shared__ char smem[];
    const uint32_t sbase = smem_u32(smem);

    const int z = blockIdx.z;
    Ahi += (size_t)z * aoz;  Alo += (size_t)z * aoz;
    Bhi += (size_t)z * boz;  Blo += (size_t)z * boz;
    const int m0 = blockIdx.x * MT, n0 = blockIdx.y * 64;

    const int tid = threadIdx.x, lane = tid & 31, wid = tid >> 5;
    const int wm = (MT == 128) ? (wid & 3) : (wid & 1);
    const int wn = (MT == 128) ? (wid >> 2) : (wid >> 1);

    const int g = lane >> 3, lr = lane & 7;
    const int grow = (g & 1) * 8 + lr;
    const int gk   = (g >> 1) * 16;

    float acc[2][NT8][4] = {};
    const int nst = K / BK;

    auto issue = [&](int s) {
        const int kt = s * BK;
        const uint32_t sb = sbase + (s % 3) * STG;
        #pragma unroll
        for (int r = 0; r < (MT * CPR) / 256; r++) {
            const int c = tid + 256 * r;
            const int row = c / CPR, col = c % CPR;
            CP_ASYNC16(sb + row * RS + col * 16,
                       &Ahi[(size_t)(m0 + row) * lda + kt + col * 8]);
            CP_ASYNC16(sb + APL + row * RS + col * 16,
                       &Alo[(size_t)(m0 + row) * lda + kt + col * 8]);
        }
        #pragma unroll
        for (int r = 0; r < (64 * CPR) / 256; r++) {
            const int c = tid + 256 * r;
            const int row = c / CPR, col = c % CPR;
            CP_ASYNC16(sb + 2 * APL + row * RS + col * 16,
                       &Bhi[(size_t)(n0 + row) * ldb + kt + col * 8]);
            CP_ASYNC16(sb + 2 * APL + BPL + row * RS + col * 16,
                       &Blo[(size_t)(n0 + row) * ldb + kt + col * 8]);
        }
    };

    issue(0); CP_COMMIT();
    if (nst > 1) issue(1);
    CP_COMMIT();

    for (int s = 0; s < nst; s++) {
        CP_WAIT1();
        __syncthreads();
        if (s + 2 < nst) issue(s + 2);
        CP_COMMIT();

        const uint32_t sb = sbase + (s % 3) * STG;
        const uint32_t ahs = sb, als = sb + APL;
        const uint32_t bhs = sb + 2 * APL, bls = bhs + BPL;
        #pragma unroll
        for (int kk = 0; kk < BK / 16; kk++) {
            const int kb = kk * 32 + gk;
            uint32_t a_hi[2][4], a_lo[2][4], b_hi[NT8 / 2][4], b_lo[NT8 / 2][4];
            #pragma unroll
            for (int mt = 0; mt < 2; mt++) {
                const uint32_t ro = (wm * 32 + mt * 16 + grow) * RS + kb;
                ldm_x4(a_hi[mt], ahs + ro);
                ldm_x4(a_lo[mt], als + ro);
            }
            #pragma unroll
            for (int ng = 0; ng < NT8 / 2; ng++) {
                const uint32_t ro = (wn * NTW + ng * 16 + grow) * RS + kb;
                ldm_x4(b_hi[ng], bhs + ro);
                ldm_x4(b_lo[ng], bls + ro);
            }
            #pragma unroll
            for (int mt = 0; mt < 2; mt++)
                #pragma unroll
                for (int nt = 0; nt < NT8; nt++) {
                    const int ng = nt >> 1, sel = nt & 1;
                    const uint32_t bh0 = b_hi[ng][sel], bh1 = b_hi[ng][sel + 2];
                    const uint32_t bl0 = b_lo[ng][sel], bl1 = b_lo[ng][sel + 2];
                    mma_bf16(acc[mt][nt], a_hi[mt], bh0, bh1);
                    mma_bf16(acc[mt][nt], a_hi[mt], bl0, bl1);
                    mma_bf16(acc[mt][nt], a_lo[mt], bh0, bh1);
                }
        }
    }

    // epilogue
    const int qr = lane >> 2, qc = (lane & 3) * 2;
    #pragma unroll
    for (int mt = 0; mt < 2; mt++) {
        const int r0 = m0 + wm * 32 + mt * 16 + qr;
        const bool z0 = ZMASK ? (rmask[r0] != 0)     : false;
        const bool z1 = ZMASK ? (rmask[r0 + 8] != 0) : false;
        #pragma unroll
        for (int nt = 0; nt < NT8; nt++) {
            const int c = n0 + wn * NTW + nt * 8 + qc;
            float b0 = 0.f, b1 = 0.f;
            if (bias) { b0 = bias[(size_t)z * bioz + c]; b1 = bias[(size_t)z * bioz + c + 1]; }
            float2 v0 = make_float2(acc[mt][nt][0] + b0, acc[mt][nt][1] + b1);
            float2 v1 = make_float2(acc[mt][nt][2] + b0, acc[mt][nt][3] + b1);
            if (z0) v0 = make_float2(0.f, 0.f);
            if (z1) v1 = make_float2(0.f, 0.f);
            const size_t o0 = (size_t)z * coz + (size_t)r0 * ldc + c;
            const size_t o1 = o0 + (size_t)8 * ldc;
            if (EMIT & 1) { *(float2*)&C[o0] = v0; *(float2*)&C[o1] = v1; }
            if (EMIT & 2) {
                split2_store(v0.x, v0.y, Chi, Clo, o0);
                split2_store(v1.x, v1.y, Chi, Clo, o1);
            }
        }
    }
}

// ======================= fused attention core (v5, R12 — proven 54.7us) ====
__global__ __launch_bounds__(256, 2) void attn_core(
    const float* __restrict__ tgt,
    const bf16* __restrict__ Qh, const bf16* __restrict__ Ql,
    const float* __restrict__ P,
    const void* __restrict__ mask_raw,
    const int* __restrict__ mask_mode,
    const float* __restrict__ ipb,
    bf16* __restrict__ Uhi, bf16* __restrict__ Ulo,
    int* __restrict__ allm)
{
    extern __shared__ float sm[];
    float4* tile4 = (float4*)sm;      // 16384 floats, swizzled (64 KB)
    float*  s_p   = sm + 16384;       // 4096 floats (16 KB)
    float*  s_la  = sm + 20480;       // 2048 partial logits (8 KB)
    float*  s_a   = sm + 22528;       // 256 softmax weights
    float*  s_c   = sm + 22784;       // 8
    float*  s_m   = sm + 22792;       // 32
    float*  s_am  = sm + 22824;       // 1

    const int i    = blockIdx.x;
    const int tid  = threadIdx.x;
    const int lane = tid & 31, w = tid >> 5;

    // async-stage tile (swizzled) and p (linear) — overlaps with c/mask below
    {
        const uint32_t tdst = smem_u32(sm);
        const float4* tg = (const float4*)(tgt + (size_t)i * (TT * DM));
        #pragma unroll
        for (int r = 0; r < 16; r++) {
            const int gg = tid + 256 * r;
            const int t = gg >> 7, k4 = gg & 127;
            CP_ASYNC16(tdst + (((t << 7) + (k4 ^ (t & 7))) << 4), tg + gg);
        }
        const uint32_t pdst = smem_u32(s_p);
        const float4* pg = (const float4*)P + (size_t)i * 1024;
        #pragma unroll
        for (int r = 0; r < 4; r++)
            CP_ASYNC16(pdst + ((tid + 256 * r) << 4), pg + tid + 256 * r);
        CP_COMMIT();
    }

    // c[h] = q_h . b_k_h (q reconstructed hi+lo)
    {
        const bf16* qh = Qh + (size_t)i * DM + w * DH;
        const bf16* ql = Ql + (size_t)i * DM + w * DH;
        const float* br = ipb + DM + w * DH;
        float q0 = __bfloat162float(qh[lane])      + __bfloat162float(ql[lane]);
        float q1 = __bfloat162float(qh[lane + 32]) + __bfloat162float(ql[lane + 32]);
        float cs = q0 * br[lane] + q1 * br[lane + 32];
        #pragma unroll
        for (int off = 16; off; off >>= 1)
            cs += __shfl_down_sync(0xffffffffu, cs, off);
        if (lane == 0) s_c[w] = cs;
    }
    if (w == 0) {
        const int mode = *mask_mode;
        unsigned mv;
        if (mode == 0)      mv = ((const unsigned char*)mask_raw)[(size_t)i * TT + lane];
        else if (mode == 1) mv = ((const unsigned*)mask_raw)[(size_t)i * TT + lane] != 0u;
        else                mv = ((const float*)mask_raw)[(size_t)i * TT + lane] != 0.f;
        s_m[lane] = mv ? 1.f : 0.f;
        unsigned bal = __ballot_sync(0xffffffffu, mv != 0);
        if (lane == 0) {
            int am = (bal == 0xffffffffu) ? 1 : 0;
            s_am[0] = (float)am;
            allm[i] = am;
        }
    }
    CP_WAIT0();
    __syncthreads();

    // logits partials: warp w = k-slab w (16 float4), lane = t, 8 heads
    {
        const int kb0 = w << 4;
        const int cx = lane & 7, tb = lane << 7;
        float s[NH] = {};
        #pragma unroll
        for (int j = 0; j < 16; j++) {
            const int k4 = kb0 + j;
            const float4 tv = tile4[tb + (k4 ^ cx)];
            #pragma unroll
            for (int h = 0; h < NH; h++) {
                const float4 pv = ((const float4*)(s_p + h * DM))[k4];
                s[h] += tv.x * pv.x + tv.y * pv.y + tv.z * pv.z + tv.w * pv.w;
            }
        }
        #pragma unroll
        for (int h = 0; h < NH; h++)
            s_la[(w << 8) + (h << 5) + lane] = s[h];
    }
    __syncthreads();

    // reduce + softmax (warp w = head w, lane = t)
    {
        const float am = s_am[0];
        float l = s_c[w];
        #pragma unroll
        for (int j = 0; j < 8; j++) l += s_la[(j << 8) + (w << 5) + lane];
        const bool inv = (s_m[lane] != 0.f) && (am == 0.f);
        l = inv ? -1e30f : l * 0.125f;
        float m = l;
        #pragma unroll
        for (int off = 16; off; off >>= 1)
            m = fmaxf(m, __shfl_xor_sync(0xffffffffu, m, off));
        float e = inv ? 0.f : __expf(l - m);
        float s = e;
        #pragma unroll
        for (int off = 16; off; off >>= 1)
            s += __shfl_xor_sync(0xffffffffu, s, off);
        s_a[(w << 5) + lane] = e / s;
    }
    __syncthreads();

    // u[h][k4] = sum_t a[h][t] * tile[t][k4]; thread = (k4, head-half)
    {
        const int k4 = tid & 127, hh = tid >> 7;
        float4 acc[4];
        #pragma unroll
        for (int h = 0; h < 4; h++) acc[h] = make_float4(0.f, 0.f, 0.f, 0.f);
        #pragma unroll 8
        for (int t = 0; t < TT; t++) {
            const float4 tv = tile4[(t << 7) + (k4 ^ (t & 7))];
            #pragma unroll
            for (int h = 0; h < 4; h++) {
                const float a = s_a[(((hh << 2) + h) << 5) + t];
                acc[h].x += a * tv.x; acc[h].y += a * tv.y;
                acc[h].z += a * tv.z; acc[h].w += a * tv.w;
            }
        }
        const size_t base = (size_t)i * (NH * DM);
        #pragma unroll
        for (int h = 0; h < 4; h++) {
            uint2 hh2, ll2; split4(acc[h], hh2, ll2);
            const size_t o = base + (size_t)(((hh << 2) + h) << 9) + (k4 << 2);
            *(uint2*)&Uhi[o] = hh2;
            *(uint2*)&Ulo[o] = ll2;
        }
    }
}

// ======================= launch ============================================
extern "C" void kernel_launch(void* const* d_in, const int* in_sizes, int n_in,
                              void* d_out, int out_size) {
    const float* src  = (const float*)d_in[0];
    const float* tgt  = (const float*)d_in[1];
    const void*  mask = d_in[2];
    const float* ipw  = (const float*)d_in[3];
    const float* ipb  = (const float*)d_in[4];
    const float* opw  = (const float*)d_in[5];
    const float* opb  = (const float*)d_in[6];
    float*       out  = (float*)d_out;

    float *P; int *AM, *MODE;
    bf16 *SRCh, *SRCl, *Qh, *Ql, *Uh, *Ul, *CTXh, *CTXl;
    bf16 *WQh, *WQl, *WKTh, *WKTl, *WVh, *WVl, *WOh, *WOl;
    cudaGetSymbolAddress((void**)&P,    g_P);
    cudaGetSymbolAddress((void**)&AM,   g_AM);
    cudaGetSymbolAddress((void**)&MODE, g_MaskMode);
    cudaGetSymbolAddress((void**)&SRCh, g_SRCh); cudaGetSymbolAddress((void**)&SRCl, g_SRCl);
    cudaGetSymbolAddress((void**)&Qh,   g_Qh);   cudaGetSymbolAddress((void**)&Ql,   g_Ql);
    cudaGetSymbolAddress((void**)&Uh,   g_Uh);   cudaGetSymbolAddress((void**)&Ul,   g_Ul);
    cudaGetSymbolAddress((void**)&CTXh, g_CTXh); cudaGetSymbolAddress((void**)&CTXl, g_CTXl);
    cudaGetSymbolAddress((void**)&WQh,  g_WQh);  cudaGetSymbolAddress((void**)&WQl,  g_WQl);
    cudaGetSymbolAddress((void**)&WKTh, g_WKTh); cudaGetSymbolAddress((void**)&WKTl, g_WKTl);
    cudaGetSymbolAddress((void**)&WVh,  g_WVh);  cudaGetSymbolAddress((void**)&WVl,  g_WVl);
    cudaGetSymbolAddress((void**)&WOh,  g_WOh);  cudaGetSymbolAddress((void**)&WOl,  g_WOl);

    const int SMG64  = 3 * (2 * 64 * 144 + 2 * 64 * 144);   // 110.6 KB, MT=64 BK=64
    const int SMG128 = 3 * (2 * 128 * 80 + 2 * 64 * 80);    // 90 KB,   MT=128 BK=32
    cudaFuncSetAttribute((const void*)hmma_gemm<64, 64, 2, false>,
                         cudaFuncAttributeMaxDynamicSharedMemorySize, SMG64);
    cudaFuncSetAttribute((const void*)hmma_gemm<128, 32, 1, false>,
                         cudaFuncAttributeMaxDynamicSharedMemorySize, SMG128);
    cudaFuncSetAttribute((const void*)hmma_gemm<64, 64, 1, true>,
                         cudaFuncAttributeMaxDynamicSharedMemorySize, SMG64);

    // 0) all prep in one launch
    prep_all<<<2049, 256>>>(src, ipw, opw, mask,
                            SRCh, SRCl, WQh, WQl, WVh, WVl, WOh, WOl,
                            WKTh, WKTl, MODE);

    // 1) Q = src @ Wq^T + bq  -> bf16 Qh/Ql only
    hmma_gemm<64, 64, 2, false><<<dim3(32, 8, 1), 256, SMG64>>>(
        SRCh, SRCl, 512, 0, WQh, WQl, 512, 0,
        nullptr, Qh, Ql, 512, 0, ipb, 0, 512, nullptr);

    // 2) P = Q_h @ WkT_h^T  -> fp32 linear [i][h][512]   (K=64, BK=32)
    hmma_gemm<128, 32, 1, false><<<dim3(16, 8, 8), 256, SMG128>>>(
        Qh, Ql, 512, 64, WKTh, WKTl, 64, 512 * 64,
        P, nullptr, nullptr, 4096, 512, nullptr, 0, 64, nullptr);

    // 3) fused attention: logits -> softmax -> U (bf16 hi/lo direct)
    const int smemA = 22825 * 4;   // ~91 KB -> 2 CTAs/SM
    cudaFuncSetAttribute(attn_core, cudaFuncAttributeMaxDynamicSharedMemorySize, smemA);
    attn_core<<<2048, 256, smemA>>>(tgt, Qh, Ql, P, mask, MODE, ipb, Uh, Ul, AM);

    // 4) ctx_h = U_h @ Wv_h^T + bv  -> bf16 CTXh/CTXl
    hmma_gemm<64, 64, 2, false><<<dim3(32, 1, 8), 256, SMG64>>>(
        Uh, Ul, 4096, 512, WVh, WVl, 512, 64 * 512,
        nullptr, CTXh, CTXl, 512, 64, ipb + 1024, 64, 512, nullptr);

    // 5) out = ctx @ Wo^T + bo, zeroing all-masked rows
    hmma_gemm<64, 64, 1, true><<<dim3(32, 8, 1), 256, SMG64>>>(
        CTXh, CTXl, 512, 0, WOh, WOl, 512, 0,
        out, nullptr, nullptr, 512, 0, opb, 0, 512, AM);
}

// round 16
// speedup vs baseline: 1.0379x; 1.0118x over previous
#include <cuda_runtime.h>
#include <cuda_bf16.h>
#include <cstdint>

// Problem constants
#define NPOS 2048   // B*S
#define DM   512
#define NH   8
#define DH   64
#define TT   32

typedef __nv_bfloat16 bf16;

// Scratch (device globals)
__device__ float g_P  [NPOS * NH * DM];   // linear: [i][h][512]
__device__ int   g_AM [NPOS];
__device__ int   g_MaskMode;
__device__ __align__(16) bf16 g_SRCh[NPOS * DM],      g_SRCl[NPOS * DM];
__device__ __align__(16) bf16 g_Qh  [NPOS * DM],      g_Ql  [NPOS * DM];
__device__ __align__(16) bf16 g_Uh  [NPOS * NH * DM], g_Ul  [NPOS * NH * DM];
__device__ __align__(16) bf16 g_CTXh[NPOS * DM],      g_CTXl[NPOS * DM];
__device__ __align__(16) bf16 g_WQh [DM * DM],        g_WQl [DM * DM];
__device__ __align__(16) bf16 g_WKTh[NH * DM * DH],   g_WKTl[NH * DM * DH];
__device__ __align__(16) bf16 g_WVh [DM * DM],        g_WVl [DM * DM];
__device__ __align__(16) bf16 g_WOh [DM * DM],        g_WOl [DM * DM];

// ======================= helpers ===========================================
__device__ __forceinline__ uint32_t smem_u32(const void* p) {
    uint32_t a;
    asm("{ .reg .u64 t; cvta.to.shared.u64 t, %1; cvt.u32.u64 %0, t; }"
        : "=r"(a) : "l"(p));
    return a;
}
__device__ __forceinline__ void ldm_x4(uint32_t* r, uint32_t addr) {
    asm volatile("ldmatrix.sync.aligned.m8n8.x4.shared.b16 {%0,%1,%2,%3}, [%4];"
                 : "=r"(r[0]), "=r"(r[1]), "=r"(r[2]), "=r"(r[3]) : "r"(addr));
}
__device__ __forceinline__ void mma_bf16(float* d, const uint32_t* a,
                                         uint32_t b0, uint32_t b1) {
    asm volatile(
        "mma.sync.aligned.m16n8k16.row.col.f32.bf16.bf16.f32 "
        "{%0,%1,%2,%3}, {%4,%5,%6,%7}, {%8,%9}, {%0,%1,%2,%3};"
        : "+f"(d[0]), "+f"(d[1]), "+f"(d[2]), "+f"(d[3])
        : "r"(a[0]), "r"(a[1]), "r"(a[2]), "r"(a[3]), "r"(b0), "r"(b1));
}
#define CP_ASYNC16(dst, src) \
    asm volatile("cp.async.cg.shared.global [%0], [%1], 16;" \
                 :: "r"(dst), "l"(src) : "memory")
#define CP_COMMIT() asm volatile("cp.async.commit_group;" ::: "memory")
#define CP_WAIT1()  asm volatile("cp.async.wait_group 1;" ::: "memory")
#define CP_WAIT0()  asm volatile("cp.async.wait_group 0;" ::: "memory")

__device__ __forceinline__ unsigned pack_bf2(bf16 a, bf16 b) {
    __nv_bfloat162 t; t.x = a; t.y = b;
    return *reinterpret_cast<unsigned*>(&t);
}
__device__ __forceinline__ void split4(float4 v, uint2& hi, uint2& lo) {
    bf16 hx = __float2bfloat16(v.x), hy = __float2bfloat16(v.y);
    bf16 hz = __float2bfloat16(v.z), hw = __float2bfloat16(v.w);
    bf16 lx = __float2bfloat16(v.x - __bfloat162float(hx));
    bf16 ly = __float2bfloat16(v.y - __bfloat162float(hy));
    bf16 lz = __float2bfloat16(v.z - __bfloat162float(hz));
    bf16 lw = __float2bfloat16(v.w - __bfloat162float(hw));
    hi = make_uint2(pack_bf2(hx, hy), pack_bf2(hz, hw));
    lo = make_uint2(pack_bf2(lx, ly), pack_bf2(lz, lw));
}
__device__ __forceinline__ void split2_store(float x, float y,
                                             bf16* hi, bf16* lo, size_t off) {
    bf16 hx = __float2bfloat16(x), hy = __float2bfloat16(y);
    bf16 lx = __float2bfloat16(x - __bfloat162float(hx));
    bf16 ly = __float2bfloat16(y - __bfloat162float(hy));
    *(uint32_t*)&hi[off] = pack_bf2(hx, hy);
    *(uint32_t*)&lo[off] = pack_bf2(lx, ly);
}

// ======================= fused prep kernel =================================
__global__ __launch_bounds__(256) void prep_all(
    const float* __restrict__ src, const float* __restrict__ ipw,
    const float* __restrict__ opw, const void* __restrict__ mask,
    bf16* __restrict__ SRCh, bf16* __restrict__ SRCl,
    bf16* __restrict__ WQh,  bf16* __restrict__ WQl,
    bf16* __restrict__ WVh,  bf16* __restrict__ WVl,
    bf16* __restrict__ WOh,  bf16* __restrict__ WOl,
    bf16* __restrict__ WKTh, bf16* __restrict__ WKTl,
    int* __restrict__ mode)
{
    const int b = blockIdx.x, tid = threadIdx.x;
    if (b < 1792) {
        const float* x; bf16 *hi, *lo; int i;
        if (b < 1024)      { x = src;             hi = SRCh; lo = SRCl; i = b * 256 + tid; }
        else if (b < 1280) { x = ipw;             hi = WQh;  lo = WQl;  i = (b - 1024) * 256 + tid; }
        else if (b < 1536) { x = ipw + 1024*512;  hi = WVh;  lo = WVl;  i = (b - 1280) * 256 + tid; }
        else               { x = opw;             hi = WOh;  lo = WOl;  i = (b - 1536) * 256 + tid; }
        float4 v = ((const float4*)x)[i];
        uint2 h, l; split4(v, h, l);
        ((uint2*)hi)[i] = h; ((uint2*)lo)[i] = l;
    } else if (b < 2048) {
        __shared__ float t[32][33];
        const int r = b - 1792;
        const int h = r >> 5, nb = (r & 15) * 32, kb = ((r >> 4) & 1) * 32;
        const int x = tid & 31, y = tid >> 5;
        for (int i = y; i < 32; i += 8)
            t[i][x] = ipw[(size_t)(512 + h * 64 + kb + i) * 512 + nb + x];
        __syncthreads();
        for (int i = y; i < 32; i += 8) {
            float v = t[x][i];
            size_t o = (size_t)h * (512 * 64) + (size_t)(nb + i) * 64 + kb + x;
            bf16 bh = __float2bfloat16(v);
            WKTh[o] = bh;
            WKTl[o] = __float2bfloat16(v - __bfloat162float(bh));
        }
    } else {
        __shared__ int flags[2];
        if (tid < 2) flags[tid] = 0;
        __syncthreads();
        const unsigned* w = (const unsigned*)mask;
        for (int j = tid; j < 16384; j += 256) {
            unsigned v = w[j];
            if (v == 0x3F800000u) atomicOr(&flags[0], 1);
            else if (v > 1u)      atomicOr(&flags[1], 1);
        }
        __syncthreads();
        if (tid == 0) *mode = flags[0] ? 2 : (flags[1] ? 0 : 1);
    }
}

// ======================= HMMA GEMM (cp.async, MT x 64 tile, BK param) ======
// C[M,N] = A[M,K] @ B[N,K]^T + bias; pre-split bf16 hi/lo planes; split
// product hi*hi + hi*lo + lo*hi. MT=128: 4Mx2N warps; MT=64: 2Mx4N warps.
// BK = k-depth per pipeline stage (32 or 64). Row stride 2*BK+16 bytes keeps
// ldmatrix conflict-free. EMIT bit0: fp32 C; bit1: bf16 hi/lo planes.
template <int MT, int BK, int EMIT, bool ZMASK>
__global__ __launch_bounds__(256, 2) void hmma_gemm(
    const bf16* __restrict__ Ahi, const bf16* __restrict__ Alo, int lda, int aoz,
    const bf16* __restrict__ Bhi, const bf16* __restrict__ Blo, int ldb, int boz,
    float* __restrict__ C, bf16* __restrict__ Chi, bf16* __restrict__ Clo,
    int ldc, int coz,
    const float* __restrict__ bias, int bioz,
    int K, const int* __restrict__ rmask)
{
    constexpr int RS  = 2 * BK + 16;        // 80 (BK=32) or 144 (BK=64)
    constexpr int APL = MT * RS;
    constexpr int BPL = 64 * RS;
    constexpr int STG = 2 * APL + 2 * BPL;
    constexpr int NTW = (MT == 128) ? 32 : 16;
    constexpr int NT8 = NTW / 8;
    constexpr int CPR = BK / 8;             // 16B chunks per row

    extern __shared__ char smem[];
    const uint32_t sbase = smem_u32(smem);

    const int z = blockIdx.z;
    Ahi += (size_t)z * aoz;  Alo += (size_t)z * aoz;
    Bhi += (size_t)z * boz;  Blo += (size_t)z * boz;
    const int m0 = blockIdx.x * MT, n0 = blockIdx.y * 64;

    const int tid = threadIdx.x, lane = tid & 31, wid = tid >> 5;
    const int wm = (MT == 128) ? (wid & 3) : (wid & 1);
    const int wn = (MT == 128) ? (wid >> 2) : (wid >> 1);

    const int g = lane >> 3, lr = lane & 7;
    const int grow = (g & 1) * 8 + lr;
    const int gk   = (g >> 1) * 16;

    float acc[2][NT8][4] = {};
    const int nst = K / BK;

    auto issue = [&](int s) {
        const int kt = s * BK;
        const uint32_t sb = sbase + (s % 3) * STG;
        #pragma unroll
        for (int r = 0; r < (MT * CPR) / 256; r++) {
            const int c = tid + 256 * r;
            const int row = c / CPR, col = c % CPR;
            CP_ASYNC16(sb + row * RS + col * 16,
                       &Ahi[(size_t)(m0 + row) * lda + kt + col * 8]);
            CP_ASYNC16(sb + APL + row * RS + col * 16,
                       &Alo[(size_t)(m0 + row) * lda + kt + col * 8]);
        }
        #pragma unroll
        for (int r = 0; r < (64 * CPR) / 256; r++) {
            const int c = tid + 256 * r;
            const int row = c / CPR, col = c % CPR;
            CP_ASYNC16(sb + 2 * APL + row * RS + col * 16,
                       &Bhi[(size_t)(n0 + row) * ldb + kt + col * 8]);
            CP_ASYNC16(sb + 2 * APL + BPL + row * RS + col * 16,
                       &Blo[(size_t)(n0 + row) * ldb + kt + col * 8]);
        }
    };

    issue(0); CP_COMMIT();
    if (nst > 1) issue(1);
    CP_COMMIT();

    for (int s = 0; s < nst; s++) {
        CP_WAIT1();
        __syncthreads();
        if (s + 2 < nst) issue(s + 2);
        CP_COMMIT();

        const uint32_t sb = sbase + (s % 3) * STG;
        const uint32_t ahs = sb, als = sb + APL;
        const uint32_t bhs = sb + 2 * APL, bls = bhs + BPL;
        #pragma unroll
        for (int kk = 0; kk < BK / 16; kk++) {
            const int kb = kk * 32 + gk;
            uint32_t a_hi[2][4], a_lo[2][4], b_hi[NT8 / 2][4], b_lo[NT8 / 2][4];
            #pragma unroll
            for (int mt = 0; mt < 2; mt++) {
                const uint32_t ro = (wm * 32 + mt * 16 + grow) * RS + kb;
                ldm_x4(a_hi[mt], ahs + ro);
                ldm_x4(a_lo[mt], als + ro);
            }
            #pragma unroll
            for (int ng = 0; ng < NT8 / 2; ng++) {
                const uint32_t ro = (wn * NTW + ng * 16 + grow) * RS + kb;
                ldm_x4(b_hi[ng], bhs + ro);
                ldm_x4(b_lo[ng], bls + ro);
            }
            #pragma unroll
            for (int mt = 0; mt < 2; mt++)
                #pragma unroll
                for (int nt = 0; nt < NT8; nt++) {
                    const int ng = nt >> 1, sel = nt & 1;
                    const uint32_t bh0 = b_hi[ng][sel], bh1 = b_hi[ng][sel + 2];
                    const uint32_t bl0 = b_lo[ng][sel], bl1 = b_lo[ng][sel + 2];
                    mma_bf16(acc[mt][nt], a_hi[mt], bh0, bh1);
                    mma_bf16(acc[mt][nt], a_hi[mt], bl0, bl1);
                    mma_bf16(acc[mt][nt], a_lo[mt], bh0, bh1);
                }
        }
    }

    // epilogue
    const int qr = lane >> 2, qc = (lane & 3) * 2;
    #pragma unroll
    for (int mt = 0; mt < 2; mt++) {
        const int r0 = m0 + wm * 32 + mt * 16 + qr;
        const bool z0 = ZMASK ? (rmask[r0] != 0)     : false;
        const bool z1 = ZMASK ? (rmask[r0 + 8] != 0) : false;
        #pragma unroll
        for (int nt = 0; nt < NT8; nt++) {
            const int c = n0 + wn * NTW + nt * 8 + qc;
            float b0 = 0.f, b1 = 0.f;
            if (bias) { b0 = bias[(size_t)z * bioz + c]; b1 = bias[(size_t)z * bioz + c + 1]; }
            float2 v0 = make_float2(acc[mt][nt][0] + b0, acc[mt][nt][1] + b1);
            float2 v1 = make_float2(acc[mt][nt][2] + b0, acc[mt][nt][3] + b1);
            if (z0) v0 = make_float2(0.f, 0.f);
            if (z1) v1 = make_float2(0.f, 0.f);
            const size_t o0 = (size_t)z * coz + (size_t)r0 * ldc + c;
            const size_t o1 = o0 + (size_t)8 * ldc;
            if (EMIT & 1) { *(float2*)&C[o0] = v0; *(float2*)&C[o1] = v1; }
            if (EMIT & 2) {
                split2_store(v0.x, v0.y, Chi, Clo, o0);
                split2_store(v1.x, v1.y, Chi, Clo, o1);
            }
        }
    }
}

// ======================= fused attention core (v5, R12 — proven 54.7us) ====
__global__ __launch_bounds__(256, 2) void attn_core(
    const float* __restrict__ tgt,
    const bf16* __restrict__ Qh, const bf16* __restrict__ Ql,
    const float* __restrict__ P,
    const void* __restrict__ mask_raw,
    const int* __restrict__ mask_mode,
    const float* __restrict__ ipb,
    bf16* __restrict__ Uhi, bf16* __restrict__ Ulo,
    int* __restrict__ allm)
{
    extern __shared__ float sm[];
    float4* tile4 = (float4*)sm;      // 16384 floats, swizzled (64 KB)
    float*  s_p   = sm + 16384;       // 4096 floats (16 KB)
    float*  s_la  = sm + 20480;       // 2048 partial logits (8 KB)
    float*  s_a   = sm + 22528;       // 256 softmax weights
    float*  s_c   = sm + 22784;       // 8
    float*  s_m   = sm + 22792;       // 32
    float*  s_am  = sm + 22824;       // 1

    const int i    = blockIdx.x;
    const int tid  = threadIdx.x;
    const int lane = tid & 31, w = tid >> 5;

    // async-stage tile (swizzled) and p (linear) — overlaps with c/mask below
    {
        const uint32_t tdst = smem_u32(sm);
        const float4* tg = (const float4*)(tgt + (size_t)i * (TT * DM));
        #pragma unroll
        for (int r = 0; r < 16; r++) {
            const int gg = tid + 256 * r;
            const int t = gg >> 7, k4 = gg & 127;
            CP_ASYNC16(tdst + (((t << 7) + (k4 ^ (t & 7))) << 4), tg + gg);
        }
        const uint32_t pdst = smem_u32(s_p);
        const float4* pg = (const float4*)P + (size_t)i * 1024;
        #pragma unroll
        for (int r = 0; r < 4; r++)
            CP_ASYNC16(pdst + ((tid + 256 * r) << 4), pg + tid + 256 * r);
        CP_COMMIT();
    }

    // c[h] = q_h . b_k_h (q reconstructed hi+lo)
    {
        const bf16* qh = Qh + (size_t)i * DM + w * DH;
        const bf16* ql = Ql + (size_t)i * DM + w * DH;
        const float* br = ipb + DM + w * DH;
        float q0 = __bfloat162float(qh[lane])      + __bfloat162float(ql[lane]);
        float q1 = __bfloat162float(qh[lane + 32]) + __bfloat162float(ql[lane + 32]);
        float cs = q0 * br[lane] + q1 * br[lane + 32];
        #pragma unroll
        for (int off = 16; off; off >>= 1)
            cs += __shfl_down_sync(0xffffffffu, cs, off);
        if (lane == 0) s_c[w] = cs;
    }
    if (w == 0) {
        const int mode = *mask_mode;
        unsigned mv;
        if (mode == 0)      mv = ((const unsigned char*)mask_raw)[(size_t)i * TT + lane];
        else if (mode == 1) mv = ((const unsigned*)mask_raw)[(size_t)i * TT + lane] != 0u;
        else                mv = ((const float*)mask_raw)[(size_t)i * TT + lane] != 0.f;
        s_m[lane] = mv ? 1.f : 0.f;
        unsigned bal = __ballot_sync(0xffffffffu, mv != 0);
        if (lane == 0) {
            int am = (bal == 0xffffffffu) ? 1 : 0;
            s_am[0] = (float)am;
            allm[i] = am;
        }
    }
    CP_WAIT0();
    __syncthreads();

    // logits partials: warp w = k-slab w (16 float4), lane = t, 8 heads
    {
        const int kb0 = w << 4;
        const int cx = lane & 7, tb = lane << 7;
        float s[NH] = {};
        #pragma unroll
        for (int j = 0; j < 16; j++) {
            const int k4 = kb0 + j;
            const float4 tv = tile4[tb + (k4 ^ cx)];
            #pragma unroll
            for (int h = 0; h < NH; h++) {
                const float4 pv = ((const float4*)(s_p + h * DM))[k4];
                s[h] += tv.x * pv.x + tv.y * pv.y + tv.z * pv.z + tv.w * pv.w;
            }
        }
        #pragma unroll
        for (int h = 0; h < NH; h++)
            s_la[(w << 8) + (h << 5) + lane] = s[h];
    }
    __syncthreads();

    // reduce + softmax (warp w = head w, lane = t)
    {
        const float am = s_am[0];
        float l = s_c[w];
        #pragma unroll
        for (int j = 0; j < 8; j++) l += s_la[(j << 8) + (w << 5) + lane];
        const bool inv = (s_m[lane] != 0.f) && (am == 0.f);
        l = inv ? -1e30f : l * 0.125f;
        float m = l;
        #pragma unroll
        for (int off = 16; off; off >>= 1)
            m = fmaxf(m, __shfl_xor_sync(0xffffffffu, m, off));
        float e = inv ? 0.f : __expf(l - m);
        float s = e;
        #pragma unroll
        for (int off = 16; off; off >>= 1)
            s += __shfl_xor_sync(0xffffffffu, s, off);
        s_a[(w << 5) + lane] = e / s;
    }
    __syncthreads();

    // u[h][k4] = sum_t a[h][t] * tile[t][k4]; thread = (k4, head-half)
    {
        const int k4 = tid & 127, hh = tid >> 7;
        float4 acc[4];
        #pragma unroll
        for (int h = 0; h < 4; h++) acc[h] = make_float4(0.f, 0.f, 0.f, 0.f);
        #pragma unroll 8
        for (int t = 0; t < TT; t++) {
            const float4 tv = tile4[(t << 7) + (k4 ^ (t & 7))];
            #pragma unroll
            for (int h = 0; h < 4; h++) {
                const float a = s_a[(((hh << 2) + h) << 5) + t];
                acc[h].x += a * tv.x; acc[h].y += a * tv.y;
                acc[h].z += a * tv.z; acc[h].w += a * tv.w;
            }
        }
        const size_t base = (size_t)i * (NH * DM);
        #pragma unroll
        for (int h = 0; h < 4; h++) {
            uint2 hh2, ll2; split4(acc[h], hh2, ll2);
            const size_t o = base + (size_t)(((hh << 2) + h) << 9) + (k4 << 2);
            *(uint2*)&Uhi[o] = hh2;
            *(uint2*)&Ulo[o] = ll2;
        }
    }
}

// ======================= launch ============================================
extern "C" void kernel_launch(void* const* d_in, const int* in_sizes, int n_in,
                              void* d_out, int out_size) {
    const float* src  = (const float*)d_in[0];
    const float* tgt  = (const float*)d_in[1];
    const void*  mask = d_in[2];
    const float* ipw  = (const float*)d_in[3];
    const float* ipb  = (const float*)d_in[4];
    const float* opw  = (const float*)d_in[5];
    const float* opb  = (const float*)d_in[6];
    float*       out  = (float*)d_out;

    float *P; int *AM, *MODE;
    bf16 *SRCh, *SRCl, *Qh, *Ql, *Uh, *Ul, *CTXh, *CTXl;
    bf16 *WQh, *WQl, *WKTh, *WKTl, *WVh, *WVl, *WOh, *WOl;
    cudaGetSymbolAddress((void**)&P,    g_P);
    cudaGetSymbolAddress((void**)&AM,   g_AM);
    cudaGetSymbolAddress((void**)&MODE, g_MaskMode);
    cudaGetSymbolAddress((void**)&SRCh, g_SRCh); cudaGetSymbolAddress((void**)&SRCl, g_SRCl);
    cudaGetSymbolAddress((void**)&Qh,   g_Qh);   cudaGetSymbolAddress((void**)&Ql,   g_Ql);
    cudaGetSymbolAddress((void**)&Uh,   g_Uh);   cudaGetSymbolAddress((void**)&Ul,   g_Ul);
    cudaGetSymbolAddress((void**)&CTXh, g_CTXh); cudaGetSymbolAddress((void**)&CTXl, g_CTXl);
    cudaGetSymbolAddress((void**)&WQh,  g_WQh);  cudaGetSymbolAddress((void**)&WQl,  g_WQl);
    cudaGetSymbolAddress((void**)&WKTh, g_WKTh); cudaGetSymbolAddress((void**)&WKTl, g_WKTl);
    cudaGetSymbolAddress((void**)&WVh,  g_WVh);  cudaGetSymbolAddress((void**)&WVl,  g_WVl);
    cudaGetSymbolAddress((void**)&WOh,  g_WOh);  cudaGetSymbolAddress((void**)&WOl,  g_WOl);

    const int SMG64  = 3 * (2 * 64 * 144 + 2 * 64 * 144);   // 110.6 KB, MT=64 BK=64
    const int SMG128 = 3 * (2 * 128 * 80 + 2 * 64 * 80);    // 90 KB,   MT=128 BK=32
    cudaFuncSetAttribute((const void*)hmma_gemm<64, 64, 2, false>,
                         cudaFuncAttributeMaxDynamicSharedMemorySize, SMG64);
    cudaFuncSetAttribute((const void*)hmma_gemm<128, 32, 1, false>,
                         cudaFuncAttributeMaxDynamicSharedMemorySize, SMG128);
    cudaFuncSetAttribute((const void*)hmma_gemm<64, 64, 1, true>,
                         cudaFuncAttributeMaxDynamicSharedMemorySize, SMG64);

    // 0) all prep in one launch
    prep_all<<<2049, 256>>>(src, ipw, opw, mask,
                            SRCh, SRCl, WQh, WQl, WVh, WVl, WOh, WOl,
                            WKTh, WKTl, MODE);

    // 1) Q = src @ Wq^T + bq  -> bf16 Qh/Ql only
    hmma_gemm<64, 64, 2, false><<<dim3(32, 8, 1), 256, SMG64>>>(
        SRCh, SRCl, 512, 0, WQh, WQl, 512, 0,
        nullptr, Qh, Ql, 512, 0, ipb, 0, 512, nullptr);

    // 2) P = Q_h @ WkT_h^T  -> fp32 linear [i][h][512]   (K=64, BK=32)
    hmma_gemm<128, 32, 1, false><<<dim3(16, 8, 8), 256, SMG128>>>(
        Qh, Ql, 512, 64, WKTh, WKTl, 64, 512 * 64,
        P, nullptr, nullptr, 4096, 512, nullptr, 0, 64, nullptr);

    // 3) fused attention: logits -> softmax -> U (bf16 hi/lo direct)
    const int smemA = 22825 * 4;   // ~91 KB -> 2 CTAs/SM
    cudaFuncSetAttribute(attn_core, cudaFuncAttributeMaxDynamicSharedMemorySize, smemA);
    attn_core<<<2048, 256, smemA>>>(tgt, Qh, Ql, P, mask, MODE, ipb, Uh, Ul, AM);

    // 4) ctx_h = U_h @ Wv_h^T + bv  -> bf16 CTXh/CTXl
    hmma_gemm<64, 64, 2, false><<<dim3(32, 1, 8), 256, SMG64>>>(
        Uh, Ul, 4096, 512, WVh, WVl, 512, 64 * 512,
        nullptr, CTXh, CTXl, 512, 64, ipb + 1024, 64, 512, nullptr);

    // 5) out = ctx @ Wo^T + bo, zeroing all-masked rows
    hmma_gemm<64, 64, 1, true><<<dim3(32, 8, 1), 256, SMG64>>>(
        CTXh, CTXl, 512, 0, WOh, WOl, 512, 0,
        out, nullptr, nullptr, 512, 0, opb, 0, 512, AM);
}

// round 17
// speedup vs baseline: 1.0381x; 1.0002x over previous
#include <cuda_runtime.h>
#include <cuda_bf16.h>
#include <cstdint>

// Problem constants
#define NPOS 2048   // B*S
#define DM   512
#define NH   8
#define DH   64
#define TT   32

typedef __nv_bfloat16 bf16;

// Scratch (device globals)
__device__ float g_P  [NPOS * NH * DM];   // linear: [i][h][512]
__device__ int   g_AM [NPOS];
__device__ int   g_MaskMode;
__device__ __align__(16) bf16 g_SRCh[NPOS * DM],      g_SRCl[NPOS * DM];
__device__ __align__(16) bf16 g_Qh  [NPOS * DM],      g_Ql  [NPOS * DM];
__device__ __align__(16) bf16 g_Uh  [NPOS * NH * DM], g_Ul  [NPOS * NH * DM];
__device__ __align__(16) bf16 g_CTXh[NPOS * DM],      g_CTXl[NPOS * DM];
__device__ __align__(16) bf16 g_WQh [DM * DM],        g_WQl [DM * DM];
__device__ __align__(16) bf16 g_WKTh[NH * DM * DH],   g_WKTl[NH * DM * DH];
__device__ __align__(16) bf16 g_WVh [DM * DM],        g_WVl [DM * DM];
__device__ __align__(16) bf16 g_WOh [DM * DM],        g_WOl [DM * DM];

// ======================= helpers ===========================================
__device__ __forceinline__ uint32_t smem_u32(const void* p) {
    uint32_t a;
    asm("{ .reg .u64 t; cvta.to.shared.u64 t, %1; cvt.u32.u64 %0, t; }"
        : "=r"(a) : "l"(p));
    return a;
}
__device__ __forceinline__ void ldm_x4(uint32_t* r, uint32_t addr) {
    asm volatile("ldmatrix.sync.aligned.m8n8.x4.shared.b16 {%0,%1,%2,%3}, [%4];"
                 : "=r"(r[0]), "=r"(r[1]), "=r"(r[2]), "=r"(r[3]) : "r"(addr));
}
__device__ __forceinline__ void mma_bf16(float* d, const uint32_t* a,
                                         uint32_t b0, uint32_t b1) {
    asm volatile(
        "mma.sync.aligned.m16n8k16.row.col.f32.bf16.bf16.f32 "
        "{%0,%1,%2,%3}, {%4,%5,%6,%7}, {%8,%9}, {%0,%1,%2,%3};"
        : "+f"(d[0]), "+f"(d[1]), "+f"(d[2]), "+f"(d[3])
        : "r"(a[0]), "r"(a[1]), "r"(a[2]), "r"(a[3]), "r"(b0), "r"(b1));
}
#define CP_ASYNC16(dst, src) \
    asm volatile("cp.async.cg.shared.global [%0], [%1], 16;" \
                 :: "r"(dst), "l"(src) : "memory")
#define CP_COMMIT() asm volatile("cp.async.commit_group;" ::: "memory")
#define CP_WAIT1()  asm volatile("cp.async.wait_group 1;" ::: "memory")
#define CP_WAIT0()  asm volatile("cp.async.wait_group 0;" ::: "memory")

__device__ __forceinline__ unsigned pack_bf2(bf16 a, bf16 b) {
    __nv_bfloat162 t; t.x = a; t.y = b;
    return *reinterpret_cast<unsigned*>(&t);
}
__device__ __forceinline__ void split4(float4 v, uint2& hi, uint2& lo) {
    bf16 hx = __float2bfloat16(v.x), hy = __float2bfloat16(v.y);
    bf16 hz = __float2bfloat16(v.z), hw = __float2bfloat16(v.w);
    bf16 lx = __float2bfloat16(v.x - __bfloat162float(hx));
    bf16 ly = __float2bfloat16(v.y - __bfloat162float(hy));
    bf16 lz = __float2bfloat16(v.z - __bfloat162float(hz));
    bf16 lw = __float2bfloat16(v.w - __bfloat162float(hw));
    hi = make_uint2(pack_bf2(hx, hy), pack_bf2(hz, hw));
    lo = make_uint2(pack_bf2(lx, ly), pack_bf2(lz, lw));
}
__device__ __forceinline__ void split2_store(float x, float y,
                                             bf16* hi, bf16* lo, size_t off) {
    bf16 hx = __float2bfloat16(x), hy = __float2bfloat16(y);
    bf16 lx = __float2bfloat16(x - __bfloat162float(hx));
    bf16 ly = __float2bfloat16(y - __bfloat162float(hy));
    *(uint32_t*)&hi[off] = pack_bf2(hx, hy);
    *(uint32_t*)&lo[off] = pack_bf2(lx, ly);
}

// ======================= fused prep kernel =================================
__global__ __launch_bounds__(256) void prep_all(
    const float* __restrict__ src, const float* __restrict__ ipw,
    const float* __restrict__ opw, const void* __restrict__ mask,
    bf16* __restrict__ SRCh, bf16* __restrict__ SRCl,
    bf16* __restrict__ WQh,  bf16* __restrict__ WQl,
    bf16* __restrict__ WVh,  bf16* __restrict__ WVl,
    bf16* __restrict__ WOh,  bf16* __restrict__ WOl,
    bf16* __restrict__ WKTh, bf16* __restrict__ WKTl,
    int* __restrict__ mode)
{
    const int b = blockIdx.x, tid = threadIdx.x;
    if (b < 1792) {
        const float* x; bf16 *hi, *lo; int i;
        if (b < 1024)      { x = src;             hi = SRCh; lo = SRCl; i = b * 256 + tid; }
        else if (b < 1280) { x = ipw;             hi = WQh;  lo = WQl;  i = (b - 1024) * 256 + tid; }
        else if (b < 1536) { x = ipw + 1024*512;  hi = WVh;  lo = WVl;  i = (b - 1280) * 256 + tid; }
        else               { x = opw;             hi = WOh;  lo = WOl;  i = (b - 1536) * 256 + tid; }
        float4 v = ((const float4*)x)[i];
        uint2 h, l; split4(v, h, l);
        ((uint2*)hi)[i] = h; ((uint2*)lo)[i] = l;
    } else if (b < 2048) {
        __shared__ float t[32][33];
        const int r = b - 1792;
        const int h = r >> 5, nb = (r & 15) * 32, kb = ((r >> 4) & 1) * 32;
        const int x = tid & 31, y = tid >> 5;
        for (int i = y; i < 32; i += 8)
            t[i][x] = ipw[(size_t)(512 + h * 64 + kb + i) * 512 + nb + x];
        __syncthreads();
        for (int i = y; i < 32; i += 8) {
            float v = t[x][i];
            size_t o = (size_t)h * (512 * 64) + (size_t)(nb + i) * 64 + kb + x;
            bf16 bh = __float2bfloat16(v);
            WKTh[o] = bh;
            WKTl[o] = __float2bfloat16(v - __bfloat162float(bh));
        }
    } else {
        __shared__ int flags[2];
        if (tid < 2) flags[tid] = 0;
        __syncthreads();
        const unsigned* w = (const unsigned*)mask;
        for (int j = tid; j < 16384; j += 256) {
            unsigned v = w[j];
            if (v == 0x3F800000u) atomicOr(&flags[0], 1);
            else if (v > 1u)      atomicOr(&flags[1], 1);
        }
        __syncthreads();
        if (tid == 0) *mode = flags[0] ? 2 : (flags[1] ? 0 : 1);
    }
}

// ======================= HMMA GEMM (cp.async, MT x 64 tile, BK param) ======
// C[M,N] = A[M,K] @ B[N,K]^T + bias; pre-split bf16 hi/lo planes; split
// product hi*hi + hi*lo + lo*hi. MT=128: 4Mx2N warps; MT=64: 2Mx4N warps.
// BK = k-depth per pipeline stage (32 or 64). Row stride 2*BK+16 bytes keeps
// ldmatrix conflict-free. EMIT bit0: fp32 C; bit1: bf16 hi/lo planes.
template <int MT, int BK, int EMIT, bool ZMASK>
__global__ __launch_bounds__(256, 2) void hmma_gemm(
    const bf16* __restrict__ Ahi, const bf16* __restrict__ Alo, int lda, int aoz,
    const bf16* __restrict__ Bhi, const bf16* __restrict__ Blo, int ldb, int boz,
    float* __restrict__ C, bf16* __restrict__ Chi, bf16* __restrict__ Clo,
    int ldc, int coz,
    const float* __restrict__ bias, int bioz,
    int K, const int* __restrict__ rmask)
{
    constexpr int RS  = 2 * BK + 16;        // 80 (BK=32) or 144 (BK=64)
    constexpr int APL = MT * RS;
    constexpr int BPL = 64 * RS;
    constexpr int STG = 2 * APL + 2 * BPL;
    constexpr int NTW = (MT == 128) ? 32 : 16;
    constexpr int NT8 = NTW / 8;
    constexpr int CPR = BK / 8;             // 16B chunks per row

    extern __shared__ char smem[];
    const uint32_t sbase = smem_u32(smem);

    const int z = blockIdx.z;
    Ahi += (size_t)z * aoz;  Alo += (size_t)z * aoz;
    Bhi += (size_t)z * boz;  Blo += (size_t)z * boz;
    const int m0 = blockIdx.x * MT, n0 = blockIdx.y * 64;

    const int tid = threadIdx.x, lane = tid & 31, wid = tid >> 5;
    const int wm = (MT == 128) ? (wid & 3) : (wid & 1);
    const int wn = (MT == 128) ? (wid >> 2) : (wid >> 1);

    const int g = lane >> 3, lr = lane & 7;
    const int grow = (g & 1) * 8 + lr;
    const int gk   = (g >> 1) * 16;

    float acc[2][NT8][4] = {};
    const int nst = K / BK;

    auto issue = [&](int s) {
        const int kt = s * BK;
        const uint32_t sb = sbase + (s % 3) * STG;
        #pragma unroll
        for (int r = 0; r < (MT * CPR) / 256; r++) {
            const int c = tid + 256 * r;
            const int row = c / CPR, col = c % CPR;
            CP_ASYNC16(sb + row * RS + col * 16,
                       &Ahi[(size_t)(m0 + row) * lda + kt + col * 8]);
            CP_ASYNC16(sb + APL + row * RS + col * 16,
                       &Alo[(size_t)(m0 + row) * lda + kt + col * 8]);
        }
        #pragma unroll
        for (int r = 0; r < (64 * CPR) / 256; r++) {
            const int c = tid + 256 * r;
            const int row = c / CPR, col = c % CPR;
            CP_ASYNC16(sb + 2 * APL + row * RS + col * 16,
                       &Bhi[(size_t)(n0 + row) * ldb + kt + col * 8]);
            CP_ASYNC16(sb + 2 * APL + BPL + row * RS + col * 16,
                       &Blo[(size_t)(n0 + row) * ldb + kt + col * 8]);
        }
    };

    issue(0); CP_COMMIT();
    if (nst > 1) issue(1);
    CP_COMMIT();

    for (int s = 0; s < nst; s++) {
        CP_WAIT1();
        __syncthreads();
        if (s + 2 < nst) issue(s + 2);
        CP_COMMIT();

        const uint32_t sb = sbase + (s % 3) * STG;
        const uint32_t ahs = sb, als = sb + APL;
        const uint32_t bhs = sb + 2 * APL, bls = bhs + BPL;
        #pragma unroll
        for (int kk = 0; kk < BK / 16; kk++) {
            const int kb = kk * 32 + gk;
            uint32_t a_hi[2][4], a_lo[2][4], b_hi[NT8 / 2][4], b_lo[NT8 / 2][4];
            #pragma unroll
            for (int mt = 0; mt < 2; mt++) {
                const uint32_t ro = (wm * 32 + mt * 16 + grow) * RS + kb;
                ldm_x4(a_hi[mt], ahs + ro);
                ldm_x4(a_lo[mt], als + ro);
            }
            #pragma unroll
            for (int ng = 0; ng < NT8 / 2; ng++) {
                const uint32_t ro = (wn * NTW + ng * 16 + grow) * RS + kb;
                ldm_x4(b_hi[ng], bhs + ro);
                ldm_x4(b_lo[ng], bls + ro);
            }
            #pragma unroll
            for (int mt = 0; mt < 2; mt++)
                #pragma unroll
                for (int nt = 0; nt < NT8; nt++) {
                    const int ng = nt >> 1, sel = nt & 1;
                    const uint32_t bh0 = b_hi[ng][sel], bh1 = b_hi[ng][sel + 2];
                    const uint32_t bl0 = b_lo[ng][sel], bl1 = b_lo[ng][sel + 2];
                    mma_bf16(acc[mt][nt], a_hi[mt], bh0, bh1);
                    mma_bf16(acc[mt][nt], a_hi[mt], bl0, bl1);
                    mma_bf16(acc[mt][nt], a_lo[mt], bh0, bh1);
                }
        }
    }

    // epilogue
    const int qr = lane >> 2, qc = (lane & 3) * 2;
    #pragma unroll
    for (int mt = 0; mt < 2; mt++) {
        const int r0 = m0 + wm * 32 + mt * 16 + qr;
        const bool z0 = ZMASK ? (rmask[r0] != 0)     : false;
        const bool z1 = ZMASK ? (rmask[r0 + 8] != 0) : false;
        #pragma unroll
        for (int nt = 0; nt < NT8; nt++) {
            const int c = n0 + wn * NTW + nt * 8 + qc;
            float b0 = 0.f, b1 = 0.f;
            if (bias) { b0 = bias[(size_t)z * bioz + c]; b1 = bias[(size_t)z * bioz + c + 1]; }
            float2 v0 = make_float2(acc[mt][nt][0] + b0, acc[mt][nt][1] + b1);
            float2 v1 = make_float2(acc[mt][nt][2] + b0, acc[mt][nt][3] + b1);
            if (z0) v0 = make_float2(0.f, 0.f);
            if (z1) v1 = make_float2(0.f, 0.f);
            const size_t o0 = (size_t)z * coz + (size_t)r0 * ldc + c;
            const size_t o1 = o0 + (size_t)8 * ldc;
            if (EMIT & 1) { *(float2*)&C[o0] = v0; *(float2*)&C[o1] = v1; }
            if (EMIT & 2) {
                split2_store(v0.x, v0.y, Chi, Clo, o0);
                split2_store(v1.x, v1.y, Chi, Clo, o1);
            }
        }
    }
}

// ======================= fused attention core (v5, R12 — proven 54.7us) ====
__global__ __launch_bounds__(256, 2) void attn_core(
    const float* __restrict__ tgt,
    const bf16* __restrict__ Qh, const bf16* __restrict__ Ql,
    const float* __restrict__ P,
    const void* __restrict__ mask_raw,
    const int* __restrict__ mask_mode,
    const float* __restrict__ ipb,
    bf16* __restrict__ Uhi, bf16* __restrict__ Ulo,
    int* __restrict__ allm)
{
    extern __shared__ float sm[];
    float4* tile4 = (float4*)sm;      // 16384 floats, swizzled (64 KB)
    float*  s_p   = sm + 16384;       // 4096 floats (16 KB)
    float*  s_la  = sm + 20480;       // 2048 partial logits (8 KB)
    float*  s_a   = sm + 22528;       // 256 softmax weights
    float*  s_c   = sm + 22784;       // 8
    float*  s_m   = sm + 22792;       // 32
    float*  s_am  = sm + 22824;       // 1

    const int i    = blockIdx.x;
    const int tid  = threadIdx.x;
    const int lane = tid & 31, w = tid >> 5;

    // async-stage tile (swizzled) and p (linear) — overlaps with c/mask below
    {
        const uint32_t tdst = smem_u32(sm);
        const float4* tg = (const float4*)(tgt + (size_t)i * (TT * DM));
        #pragma unroll
        for (int r = 0; r < 16; r++) {
            const int gg = tid + 256 * r;
            const int t = gg >> 7, k4 = gg & 127;
            CP_ASYNC16(tdst + (((t << 7) + (k4 ^ (t & 7))) << 4), tg + gg);
        }
        const uint32_t pdst = smem_u32(s_p);
        const float4* pg = (const float4*)P + (size_t)i * 1024;
        #pragma unroll
        for (int r = 0; r < 4; r++)
            CP_ASYNC16(pdst + ((tid + 256 * r) << 4), pg + tid + 256 * r);
        CP_COMMIT();
    }

    // c[h] = q_h . b_k_h (q reconstructed hi+lo)
    {
        const bf16* qh = Qh + (size_t)i * DM + w * DH;
        const bf16* ql = Ql + (size_t)i * DM + w * DH;
        const float* br = ipb + DM + w * DH;
        float q0 = __bfloat162float(qh[lane])      + __bfloat162float(ql[lane]);
        float q1 = __bfloat162float(qh[lane + 32]) + __bfloat162float(ql[lane + 32]);
        float cs = q0 * br[lane] + q1 * br[lane + 32];
        #pragma unroll
        for (int off = 16; off; off >>= 1)
            cs += __shfl_down_sync(0xffffffffu, cs, off);
        if (lane == 0) s_c[w] = cs;
    }
    if (w == 0) {
        const int mode = *mask_mode;
        unsigned mv;
        if (mode == 0)      mv = ((const unsigned char*)mask_raw)[(size_t)i * TT + lane];
        else if (mode == 1) mv = ((const unsigned*)mask_raw)[(size_t)i * TT + lane] != 0u;
        else                mv = ((const float*)mask_raw)[(size_t)i * TT + lane] != 0.f;
        s_m[lane] = mv ? 1.f : 0.f;
        unsigned bal = __ballot_sync(0xffffffffu, mv != 0);
        if (lane == 0) {
            int am = (bal == 0xffffffffu) ? 1 : 0;
            s_am[0] = (float)am;
            allm[i] = am;
        }
    }
    CP_WAIT0();
    __syncthreads();

    // logits partials: warp w = k-slab w (16 float4), lane = t, 8 heads
    {
        const int kb0 = w << 4;
        const int cx = lane & 7, tb = lane << 7;
        float s[NH] = {};
        #pragma unroll
        for (int j = 0; j < 16; j++) {
            const int k4 = kb0 + j;
            const float4 tv = tile4[tb + (k4 ^ cx)];
            #pragma unroll
            for (int h = 0; h < NH; h++) {
                const float4 pv = ((const float4*)(s_p + h * DM))[k4];
                s[h] += tv.x * pv.x + tv.y * pv.y + tv.z * pv.z + tv.w * pv.w;
            }
        }
        #pragma unroll
        for (int h = 0; h < NH; h++)
            s_la[(w << 8) + (h << 5) + lane] = s[h];
    }
    __syncthreads();

    // reduce + softmax (warp w = head w, lane = t)
    {
        const float am = s_am[0];
        float l = s_c[w];
        #pragma unroll
        for (int j = 0; j < 8; j++) l += s_la[(j << 8) + (w << 5) + lane];
        const bool inv = (s_m[lane] != 0.f) && (am == 0.f);
        l = inv ? -1e30f : l * 0.125f;
        float m = l;
        #pragma unroll
        for (int off = 16; off; off >>= 1)
            m = fmaxf(m, __shfl_xor_sync(0xffffffffu, m, off));
        float e = inv ? 0.f : __expf(l - m);
        float s = e;
        #pragma unroll
        for (int off = 16; off; off >>= 1)
            s += __shfl_xor_sync(0xffffffffu, s, off);
        s_a[(w << 5) + lane] = e / s;
    }
    __syncthreads();

    // u[h][k4] = sum_t a[h][t] * tile[t][k4]; thread = (k4, head-half)
    {
        const int k4 = tid & 127, hh = tid >> 7;
        float4 acc[4];
        #pragma unroll
        for (int h = 0; h < 4; h++) acc[h] = make_float4(0.f, 0.f, 0.f, 0.f);
        #pragma unroll 8
        for (int t = 0; t < TT; t++) {
            const float4 tv = tile4[(t << 7) + (k4 ^ (t & 7))];
            #pragma unroll
            for (int h = 0; h < 4; h++) {
                const float a = s_a[(((hh << 2) + h) << 5) + t];
                acc[h].x += a * tv.x; acc[h].y += a * tv.y;
                acc[h].z += a * tv.z; acc[h].w += a * tv.w;
            }
        }
        const size_t base = (size_t)i * (NH * DM);
        #pragma unroll
        for (int h = 0; h < 4; h++) {
            uint2 hh2, ll2; split4(acc[h], hh2, ll2);
            const size_t o = base + (size_t)(((hh << 2) + h) << 9) + (k4 << 2);
            *(uint2*)&Uhi[o] = hh2;
            *(uint2*)&Ulo[o] = ll2;
        }
    }
}

// ======================= launch ============================================
extern "C" void kernel_launch(void* const* d_in, const int* in_sizes, int n_in,
                              void* d_out, int out_size) {
    const float* src  = (const float*)d_in[0];
    const float* tgt  = (const float*)d_in[1];
    const void*  mask = d_in[2];
    const float* ipw  = (const float*)d_in[3];
    const float* ipb  = (const float*)d_in[4];
    const float* opw  = (const float*)d_in[5];
    const float* opb  = (const float*)d_in[6];
    float*       out  = (float*)d_out;

    float *P; int *AM, *MODE;
    bf16 *SRCh, *SRCl, *Qh, *Ql, *Uh, *Ul, *CTXh, *CTXl;
    bf16 *WQh, *WQl, *WKTh, *WKTl, *WVh, *WVl, *WOh, *WOl;
    cudaGetSymbolAddress((void**)&P,    g_P);
    cudaGetSymbolAddress((void**)&AM,   g_AM);
    cudaGetSymbolAddress((void**)&MODE, g_MaskMode);
    cudaGetSymbolAddress((void**)&SRCh, g_SRCh); cudaGetSymbolAddress((void**)&SRCl, g_SRCl);
    cudaGetSymbolAddress((void**)&Qh,   g_Qh);   cudaGetSymbolAddress((void**)&Ql,   g_Ql);
    cudaGetSymbolAddress((void**)&Uh,   g_Uh);   cudaGetSymbolAddress((void**)&Ul,   g_Ul);
    cudaGetSymbolAddress((void**)&CTXh, g_CTXh); cudaGetSymbolAddress((void**)&CTXl, g_CTXl);
    cudaGetSymbolAddress((void**)&WQh,  g_WQh);  cudaGetSymbolAddress((void**)&WQl,  g_WQl);
    cudaGetSymbolAddress((void**)&WKTh, g_WKTh); cudaGetSymbolAddress((void**)&WKTl, g_WKTl);
    cudaGetSymbolAddress((void**)&WVh,  g_WVh);  cudaGetSymbolAddress((void**)&WVl,  g_WVl);
    cudaGetSymbolAddress((void**)&WOh,  g_WOh);  cudaGetSymbolAddress((void**)&WOl,  g_WOl);

    const int SMG64  = 3 * (2 * 64 * 144 + 2 * 64 * 144);   // 110.6 KB, MT=64 BK=64
    const int SMG128 = 3 * (2 * 128 * 80 + 2 * 64 * 80);    // 90 KB,   MT=128 BK=32
    cudaFuncSetAttribute((const void*)hmma_gemm<64, 64, 2, false>,
                         cudaFuncAttributeMaxDynamicSharedMemorySize, SMG64);
    cudaFuncSetAttribute((const void*)hmma_gemm<128, 32, 1, false>,
                         cudaFuncAttributeMaxDynamicSharedMemorySize, SMG128);
    cudaFuncSetAttribute((const void*)hmma_gemm<64, 64, 1, true>,
                         cudaFuncAttributeMaxDynamicSharedMemorySize, SMG64);

    // 0) all prep in one launch
    prep_all<<<2049, 256>>>(src, ipw, opw, mask,
                            SRCh, SRCl, WQh, WQl, WVh, WVl, WOh, WOl,
                            WKTh, WKTl, MODE);

    // 1) Q = src @ Wq^T + bq  -> bf16 Qh/Ql only
    hmma_gemm<64, 64, 2, false><<<dim3(32, 8, 1), 256, SMG64>>>(
        SRCh, SRCl, 512, 0, WQh, WQl, 512, 0,
        nullptr, Qh, Ql, 512, 0, ipb, 0, 512, nullptr);

    // 2) P = Q_h @ WkT_h^T  -> fp32 linear [i][h][512]   (K=64, BK=32)
    hmma_gemm<128, 32, 1, false><<<dim3(16, 8, 8), 256, SMG128>>>(
        Qh, Ql, 512, 64, WKTh, WKTl, 64, 512 * 64,
        P, nullptr, nullptr, 4096, 512, nullptr, 0, 64, nullptr);

    // 3) fused attention: logits -> softmax -> U (bf16 hi/lo direct)
    const int smemA = 22825 * 4;   // ~91 KB -> 2 CTAs/SM
    cudaFuncSetAttribute(attn_core, cudaFuncAttributeMaxDynamicSharedMemorySize, smemA);
    attn_core<<<2048, 256, smemA>>>(tgt, Qh, Ql, P, mask, MODE, ipb, Uh, Ul, AM);

    // 4) ctx_h = U_h @ Wv_h^T + bv  -> bf16 CTXh/CTXl
    hmma_gemm<64, 64, 2, false><<<dim3(32, 1, 8), 256, SMG64>>>(
        Uh, Ul, 4096, 512, WVh, WVl, 512, 64 * 512,
        nullptr, CTXh, CTXl, 512, 64, ipb + 1024, 64, 512, nullptr);

    // 5) out = ctx @ Wo^T + bo, zeroing all-masked rows
    hmma_gemm<64, 64, 1, true><<<dim3(32, 8, 1), 256, SMG64>>>(
        CTXh, CTXl, 512, 0, WOh, WOl, 512, 0,
        out, nullptr, nullptr, 512, 0, opb, 0, 512, AM);
}